// round 4
// baseline (speedup 1.0000x reference)
#include <cuda_runtime.h>
#include <cuda_fp16.h>
#include <mma.h>
using namespace nvcuda;

#define NV 20000
#define EE 320000
#define DD 128
#define HD 512
#define LL 3
#define MTILES 157
#define NV2 (MTILES * 128)
#define EPS_ 1.1920929e-07f

// ---------------- static device scratch ----------------
__device__ float  g_x  [NV2 * DD];
__device__ __half g_xh [NV2 * DD];
__device__ __half g_xph[(size_t)NV2 * HD];
__device__ __half g_h1h[NV2 * DD];
__device__ __half g_Wg [LL * DD * HD];
__device__ __half g_W1h[LL * DD * DD];
__device__ __half g_W2h[LL * DD * DD];
__device__ float  g_as[NV * 4];
__device__ float  g_ad[NV * 4];
__device__ int    g_rowptr[NV + 1];
__device__ int    g_deg[NV];
__device__ int    g_cursor[NV];
__device__ int    g_col[EE + NV];
__device__ int    g_is64;

__device__ __forceinline__ int edge_at(const void* ei, long long idx) {
    return g_is64 ? (int)((const long long*)ei)[idx] : ((const int*)ei)[idx];
}

// ---------------- fused setup ----------------
#define WHALF ((LL * DD * HD + 2 * LL * DD * DD) / 2)

__global__ void k_setup(const float4* __restrict__ x,
                        const float* __restrict__ Wg,
                        const float* __restrict__ W1,
                        const float* __restrict__ W2,
                        const unsigned* __restrict__ ei_w) {
    int i = blockIdx.x * 256 + threadIdx.x;
    if (i < NV * DD / 4) {
        float4 v = x[i];
        ((float4*)g_x)[i] = v;
        ((__half2*)g_xh)[i * 2]     = __floats2half2_rn(v.x, v.y);
        ((__half2*)g_xh)[i * 2 + 1] = __floats2half2_rn(v.z, v.w);
    }
    if (i < WHALF) {
        int j = i * 2;
        const float* src; __half* dst; int off;
        if (j < LL * DD * HD)                     { src = Wg; dst = g_Wg;  off = j; }
        else if (j < LL * DD * HD + LL * DD * DD) { src = W1; dst = g_W1h; off = j - LL * DD * HD; }
        else                                      { src = W2; dst = g_W2h; off = j - LL * DD * HD - LL * DD * DD; }
        float2 v = *(const float2*)(src + off);
        *(__half2*)(dst + off) = __floats2half2_rn(v.x, v.y);
    }
    if (i < NV) g_deg[i] = 1;
    if (blockIdx.x == 0) {
        __shared__ unsigned acc;
        if (threadIdx.x == 0) acc = 0u;
        __syncthreads();
        unsigned v = 0;
        for (int k = threadIdx.x; k < 2048; k += 256) v |= ei_w[2 * k + 1];
        if (v) atomicOr(&acc, 1u);
        __syncthreads();
        if (threadIdx.x == 0) g_is64 = (acc == 0u) ? 1 : 0;
    }
}

// ---------------- CSR build ----------------
__global__ void k_count(const void* ei) {
    int e = (blockIdx.x * 256 + threadIdx.x) * 2;
    if (e < EE) {
        int d0, d1;
        if (g_is64) {
            longlong2 v = ((const longlong2*)ei)[(EE + e) >> 1];
            d0 = (int)v.x; d1 = (int)v.y;
        } else {
            int2 v = ((const int2*)ei)[(EE + e) >> 1];
            d0 = v.x; d1 = v.y;
        }
        atomicAdd(&g_deg[d0], 1);
        atomicAdd(&g_deg[d1], 1);
    }
}

// scan + fill (self loop at slot 0, cursor init) fused
__global__ __launch_bounds__(1024) void k_scan() {
    const int PER = 20;
    __shared__ int wsum[32];
    int t = threadIdx.x, lane = t & 31, w = t >> 5;
    int v[PER];
    int base = t * PER;
    int run = 0;
    if (base < NV) {
        const int4* p = (const int4*)(g_deg + base);
#pragma unroll
        for (int q = 0; q < 5; q++) {
            int4 d = p[q];
            run += d.x; v[q * 4 + 0] = run;
            run += d.y; v[q * 4 + 1] = run;
            run += d.z; v[q * 4 + 2] = run;
            run += d.w; v[q * 4 + 3] = run;
        }
    } else {
#pragma unroll
        for (int q = 0; q < PER; q++) v[q] = 0;
    }
    int tot = run, sc = tot;
#pragma unroll
    for (int o = 1; o < 32; o <<= 1) {
        int u = __shfl_up_sync(0xffffffffu, sc, o);
        if (lane >= o) sc += u;
    }
    if (lane == 31) wsum[w] = sc;
    __syncthreads();
    if (w == 0) {
        int s = wsum[lane];
#pragma unroll
        for (int o = 1; o < 32; o <<= 1) {
            int u = __shfl_up_sync(0xffffffffu, s, o);
            if (lane >= o) s += u;
        }
        wsum[lane] = s;
    }
    __syncthreads();
    int throff = ((w > 0) ? wsum[w - 1] : 0) + sc - tot;
    if (t == 0) g_rowptr[0] = 0;
    if (base < NV) {
#pragma unroll
        for (int q = 0; q < PER; q++) {
            int idx = base + q;
            int startq = throff + (q > 0 ? v[q - 1] : 0);
            g_rowptr[idx + 1] = throff + v[q];
            g_col[startq] = idx;        // self loop
            g_cursor[idx] = startq + 1;
        }
    }
}
__global__ void k_scatter(const void* ei) {
    int e = (blockIdx.x * 256 + threadIdx.x) * 2;
    if (e < EE) {
        int s0, s1, d0, d1;
        if (g_is64) {
            longlong2 sv = ((const longlong2*)ei)[e >> 1];
            longlong2 dv = ((const longlong2*)ei)[(EE + e) >> 1];
            s0 = (int)sv.x; s1 = (int)sv.y; d0 = (int)dv.x; d1 = (int)dv.y;
        } else {
            int2 sv = ((const int2*)ei)[e >> 1];
            int2 dv = ((const int2*)ei)[(EE + e) >> 1];
            s0 = sv.x; s1 = sv.y; d0 = dv.x; d1 = dv.y;
        }
        g_col[atomicAdd(&g_cursor[d0], 1)] = s0;
        g_col[atomicAdd(&g_cursor[d1], 1)] = s1;
    }
}

// ---------------- fp16 tensor-core GEMM, K=128 smem resident ----------------
// mode 0: write fp16 Ch; if atts: fused attention dots (head = blockIdx.x)
// mode 1: relu -> fp16 Ch
// mode 2: residual + RMSNorm; outF? write fp32 outF (final) : write g_x + g_xh
#define GSMEM 78336

__global__ __launch_bounds__(256) void gemm_h(
    const __half* __restrict__ A, const __half* __restrict__ B,
    const float* __restrict__ bias, __half* __restrict__ Ch,
    const float* __restrict__ nw,
    const float* __restrict__ atts, const float* __restrict__ attd,
    float* __restrict__ outF, int Ncols, int mode)
{
    extern __shared__ char dsm[];
    __half* As = (__half*)dsm;
    __half* Bs = As + 128 * 136;
    float*  Brep = (float*)(dsm + 2 * 128 * 136 * 2);
    float*  stage = (float*)dsm;

    int bm = blockIdx.y * 128, bn = blockIdx.x * 128;
    int t = threadIdx.x, warp = t >> 5, lane = t & 31;
    int wr = warp & 1, wc = warp >> 1;

    for (int i = t; i < 16 * 128; i += 256) {
        int r = i >> 7, c = i & 127;
        Brep[r * 136 + c] = bias ? bias[bn + c] : 0.f;
    }
    __syncthreads();

    wmma::fragment<wmma::accumulator, 16, 16, 16, float> acc[4][2];
#pragma unroll
    for (int fr = 0; fr < 4; fr++)
#pragma unroll
        for (int fc = 0; fc < 2; fc++)
            wmma::load_matrix_sync(acc[fr][fc], &Brep[wc * 32 + fc * 16], 136,
                                   wmma::mem_row_major);

#pragma unroll
    for (int i = 0; i < 8; i++) {
        int idx = t + i * 256;
        int r = idx >> 4, c8 = (idx & 15) * 8;
        *(uint4*)(As + r * 136 + c8) = *(const uint4*)(A + (size_t)(bm + r) * 128 + c8);
        *(uint4*)(Bs + r * 136 + c8) = *(const uint4*)(B + (size_t)r * Ncols + bn + c8);
    }
    __syncthreads();

#pragma unroll
    for (int k = 0; k < 8; k++) {
        wmma::fragment<wmma::matrix_a, 16, 16, 16, __half, wmma::row_major> af[4];
        wmma::fragment<wmma::matrix_b, 16, 16, 16, __half, wmma::row_major> bf[2];
#pragma unroll
        for (int fr = 0; fr < 4; fr++)
            wmma::load_matrix_sync(af[fr], &As[(wr * 64 + fr * 16) * 136 + k * 16], 136);
#pragma unroll
        for (int fc = 0; fc < 2; fc++)
            wmma::load_matrix_sync(bf[fc], &Bs[(k * 16) * 136 + wc * 32 + fc * 16], 136);
#pragma unroll
        for (int fr = 0; fr < 4; fr++)
#pragma unroll
            for (int fc = 0; fc < 2; fc++)
                wmma::mma_sync(acc[fr][fc], af[fr], bf[fc], acc[fr][fc]);
    }
    __syncthreads();

    if (mode == 2) {
#pragma unroll
        for (int fr = 0; fr < 4; fr++)
#pragma unroll
            for (int fc = 0; fc < 2; fc++)
                wmma::store_matrix_sync(&stage[(wr * 64 + fr * 16) * 132 + wc * 32 + fc * 16],
                                        acc[fr][fc], 132, wmma::mem_row_major);
        __syncthreads();
        float4 nwv = *(const float4*)&nw[lane * 4];
        for (int r = warp; r < 128; r += 8) {
            size_t row = (size_t)(bm + r);
            float4 xr = *(const float4*)&g_x[row * 128 + lane * 4];
            float4 st = *(const float4*)&stage[r * 132 + lane * 4];
            float v0 = xr.x + st.x, v1 = xr.y + st.y, v2 = xr.z + st.z, v3 = xr.w + st.w;
            float ss = v0 * v0 + v1 * v1 + v2 * v2 + v3 * v3;
#pragma unroll
            for (int o = 16; o; o >>= 1) ss += __shfl_xor_sync(0xffffffffu, ss, o);
            float rr = rsqrtf(ss * (1.0f / DD) + EPS_);
            float o0 = v0 * rr * nwv.x, o1 = v1 * rr * nwv.y;
            float o2 = v2 * rr * nwv.z, o3 = v3 * rr * nwv.w;
            if (outF) {
                if (row < NV)
                    *(float4*)&outF[row * 128 + lane * 4] = make_float4(o0, o1, o2, o3);
            } else {
                *(float4*)&g_x[row * 128 + lane * 4] = make_float4(o0, o1, o2, o3);
                __half2 h0 = __floats2half2_rn(o0, o1);
                __half2 h1 = __floats2half2_rn(o2, o3);
                uint2 packed;
                packed.x = *(unsigned*)&h0;
                packed.y = *(unsigned*)&h1;
                *(uint2*)&g_xh[row * 128 + lane * 4] = packed;
            }
        }
    } else {
        if (mode == 1) {
#pragma unroll
            for (int fr = 0; fr < 4; fr++)
#pragma unroll
                for (int fc = 0; fc < 2; fc++)
#pragma unroll
                    for (int i = 0; i < acc[fr][fc].num_elements; i++)
                        acc[fr][fc].x[i] = fmaxf(acc[fr][fc].x[i], 0.f);
        }
        float* ws = stage + warp * 2304;  // 64x36 per warp
#pragma unroll
        for (int fr = 0; fr < 4; fr++)
#pragma unroll
            for (int fc = 0; fc < 2; fc++)
                wmma::store_matrix_sync(&ws[fr * 16 * 36 + fc * 16], acc[fr][fc], 36,
                                        wmma::mem_row_major);
        __syncwarp();
        // vectorized fp16 store: 4 cols per op
        for (int i = lane; i < 64 * 8; i += 32) {
            int r = i >> 3, c4 = (i & 7) * 4;
            __half2 h0 = __floats2half2_rn(ws[r * 36 + c4], ws[r * 36 + c4 + 1]);
            __half2 h1 = __floats2half2_rn(ws[r * 36 + c4 + 2], ws[r * 36 + c4 + 3]);
            uint2 packed;
            packed.x = *(unsigned*)&h0;
            packed.y = *(unsigned*)&h1;
            *(uint2*)(Ch + (size_t)(bm + wr * 64 + r) * Ncols + bn + wc * 32 + c4) = packed;
        }
        if (mode == 0 && atts) {
            __syncthreads();  // all warps' ws staged
            int h = blockIdx.x;
            float as0 = atts[h * 128 + lane],      as1 = atts[h * 128 + 32 + lane];
            float as2 = atts[h * 128 + 64 + lane], as3 = atts[h * 128 + 96 + lane];
            float ad0 = attd[h * 128 + lane],      ad1 = attd[h * 128 + 32 + lane];
            float ad2 = attd[h * 128 + 64 + lane], ad3 = attd[h * 128 + 96 + lane];
            for (int rr = 0; rr < 16; rr++) {
                int r = warp * 16 + rr;
                int rh = r >> 6, rl = (r & 63) * 36 + lane;
                float v0 = stage[(rh + 0) * 2304 + rl];
                float v1 = stage[(rh + 2) * 2304 + rl];
                float v2 = stage[(rh + 4) * 2304 + rl];
                float v3 = stage[(rh + 6) * 2304 + rl];
                float ps = v0 * as0 + v1 * as1 + v2 * as2 + v3 * as3;
                float pd = v0 * ad0 + v1 * ad1 + v2 * ad2 + v3 * ad3;
#pragma unroll
                for (int o = 16; o; o >>= 1) {
                    ps += __shfl_xor_sync(0xffffffffu, ps, o);
                    pd += __shfl_xor_sync(0xffffffffu, pd, o);
                }
                int n = bm + r;
                if (lane == 0 && n < NV) {
                    g_as[n * 4 + h] = ps;
                    g_ad[n * 4 + h] = pd;
                }
            }
        }
    }
}

__device__ __forceinline__ float lrelu(float x) { return x > 0.f ? x : 0.2f * x; }

__device__ __forceinline__ void comb(float& m, float& s, float m2, float s2) {
    float M = fmaxf(m, m2);
    s = s * __expf(m - M) + s2 * __expf(m2 - M);
    m = M;
}
__device__ __forceinline__ float blk_max4(float v, float* sh) {
#pragma unroll
    for (int o = 16; o; o >>= 1) v = fmaxf(v, __shfl_xor_sync(0xffffffffu, v, o));
    int w = threadIdx.x >> 5;
    if ((threadIdx.x & 31) == 0) sh[w] = v;
    __syncthreads();
    float r = fmaxf(fmaxf(sh[0], sh[1]), fmaxf(sh[2], sh[3]));
    __syncthreads();
    return r;
}
__device__ __forceinline__ float blk_sum4(float v, float* sh) {
#pragma unroll
    for (int o = 16; o; o >>= 1) v += __shfl_xor_sync(0xffffffffu, v, o);
    int w = threadIdx.x >> 5;
    if ((threadIdx.x & 31) == 0) sh[w] = v;
    __syncthreads();
    float r = sh[0] + sh[1] + sh[2] + sh[3];
    __syncthreads();
    return r;
}

// ---------------- fused GAT aggregation ----------------
__global__ __launch_bounds__(128) void k_agg(const float* __restrict__ bias,
                                             const float* __restrict__ nw) {
    int n = blockIdx.x, t = threadIdx.x;
    int start = g_rowptr[n];
    int deg = g_rowptr[n + 1] - start;

    __shared__ float shr[4];
    __shared__ float smm[4][4], sms[4][4];
    __shared__ float sh_alpha[128][4];
    __shared__ int sh_src[128];
    __shared__ float xatt[4][128];
    __shared__ float shred[128];

    float4 adv = *(const float4*)&g_ad[n * 4];

    if (deg <= 128) {
        // ---- single-pass softmax: thread t owns edge t ----
        float e0 = -1e30f, e1 = -1e30f, e2 = -1e30f, e3 = -1e30f;
        if (t < deg) {
            int src = g_col[start + t];
            sh_src[t] = src;
            float4 asv = *(const float4*)&g_as[src * 4];
            e0 = lrelu(asv.x + adv.x);
            e1 = lrelu(asv.y + adv.y);
            e2 = lrelu(asv.z + adv.z);
            e3 = lrelu(asv.w + adv.w);
        }
        float M0 = blk_max4(e0, shr), M1 = blk_max4(e1, shr);
        float M2 = blk_max4(e2, shr), M3 = blk_max4(e3, shr);
        float x0 = (t < deg) ? __expf(e0 - M0) : 0.f;
        float x1 = (t < deg) ? __expf(e1 - M1) : 0.f;
        float x2 = (t < deg) ? __expf(e2 - M2) : 0.f;
        float x3 = (t < deg) ? __expf(e3 - M3) : 0.f;
        float S0 = blk_sum4(x0, shr), S1 = blk_sum4(x1, shr);
        float S2 = blk_sum4(x2, shr), S3 = blk_sum4(x3, shr);
        if (t < deg) {
            sh_alpha[t][0] = x0 / S0;
            sh_alpha[t][1] = x1 / S1;
            sh_alpha[t][2] = x2 / S2;
            sh_alpha[t][3] = x3 / S3;
        }
        __syncthreads();
        int h = t >> 5, q = t & 31;
        float4 acc4 = make_float4(0.f, 0.f, 0.f, 0.f);
        for (int jj = 0; jj < deg; jj++) {
            float al = sh_alpha[jj][h];
            uint2 raw = *(const uint2*)(g_xph + (size_t)sh_src[jj] * HD + h * 128 + q * 4);
            float2 f0 = __half22float2(*(__half2*)&raw.x);
            float2 f1 = __half22float2(*(__half2*)&raw.y);
            acc4.x += al * f0.x;
            acc4.y += al * f0.y;
            acc4.z += al * f1.x;
            acc4.w += al * f1.y;
        }
        *(float4*)&xatt[h][q * 4] = acc4;
        __syncthreads();
    } else {
        // ---- fallback: online two-pass ----
        float m[4] = {-1e30f, -1e30f, -1e30f, -1e30f};
        float s[4] = {0.f, 0.f, 0.f, 0.f};
        for (int j = t; j < deg; j += 128) {
            int src = g_col[start + j];
            float4 asv = *(const float4*)&g_as[src * 4];
            float e[4] = {lrelu(asv.x + adv.x), lrelu(asv.y + adv.y),
                          lrelu(asv.z + adv.z), lrelu(asv.w + adv.w)};
#pragma unroll
            for (int h = 0; h < 4; h++) comb(m[h], s[h], e[h], 1.f);
        }
        int lane = t & 31, w = t >> 5;
#pragma unroll
        for (int h = 0; h < 4; h++) {
#pragma unroll
            for (int o = 16; o; o >>= 1) {
                float m2 = __shfl_xor_sync(0xffffffffu, m[h], o);
                float s2 = __shfl_xor_sync(0xffffffffu, s[h], o);
                comb(m[h], s[h], m2, s2);
            }
            if (lane == 0) { smm[w][h] = m[h]; sms[w][h] = s[h]; }
        }
        __syncthreads();
        float M[4], inv[4];
#pragma unroll
        for (int h = 0; h < 4; h++) {
            float Mx = fmaxf(fmaxf(smm[0][h], smm[1][h]), fmaxf(smm[2][h], smm[3][h]));
            float S = sms[0][h] * __expf(smm[0][h] - Mx) + sms[1][h] * __expf(smm[1][h] - Mx)
                    + sms[2][h] * __expf(smm[2][h] - Mx) + sms[3][h] * __expf(smm[3][h] - Mx);
            M[h] = Mx;
            inv[h] = 1.f / S;
        }
        int h = t >> 5, q = t & 31;
        float4 acc4 = make_float4(0.f, 0.f, 0.f, 0.f);
        for (int c0 = 0; c0 < deg; c0 += 128) {
            int j = c0 + t;
            if (j < deg) {
                int src = g_col[start + j];
                sh_src[t] = src;
                float4 asv = *(const float4*)&g_as[src * 4];
                sh_alpha[t][0] = __expf(lrelu(asv.x + adv.x) - M[0]) * inv[0];
                sh_alpha[t][1] = __expf(lrelu(asv.y + adv.y) - M[1]) * inv[1];
                sh_alpha[t][2] = __expf(lrelu(asv.z + adv.z) - M[2]) * inv[2];
                sh_alpha[t][3] = __expf(lrelu(asv.w + adv.w) - M[3]) * inv[3];
            }
            __syncthreads();
            int cnt = min(128, deg - c0);
            for (int jj = 0; jj < cnt; jj++) {
                float al = sh_alpha[jj][h];
                uint2 raw = *(const uint2*)(g_xph + (size_t)sh_src[jj] * HD + h * 128 + q * 4);
                float2 f0 = __half22float2(*(__half2*)&raw.x);
                float2 f1 = __half22float2(*(__half2*)&raw.y);
                acc4.x += al * f0.x;
                acc4.y += al * f0.y;
                acc4.z += al * f1.x;
                acc4.w += al * f1.y;
            }
            __syncthreads();
        }
        *(float4*)&xatt[h][q * 4] = acc4;
        __syncthreads();
    }

    float a = 0.25f * (xatt[0][t] + xatt[1][t] + xatt[2][t] + xatt[3][t]);
    float v = g_x[n * DD + t] + a + bias[t];
    shred[t] = v * v;
    __syncthreads();
#pragma unroll
    for (int o = 64; o; o >>= 1) {
        if (t < o) shred[t] += shred[t + o];
        __syncthreads();
    }
    float r = rsqrtf(shred[0] * (1.0f / DD) + EPS_);
    float o = v * r * nw[t];
    g_x[n * DD + t] = o;
    g_xh[n * DD + t] = __float2half(o);
}

// ---------------- host ----------------
extern "C" void kernel_launch(void* const* d_in, const int* in_sizes, int n_in,
                              void* d_out, int out_size) {
    const float* x        = (const float*)d_in[0];
    const float* W_gat    = (const float*)d_in[1];
    const float* att_src  = (const float*)d_in[2];
    const float* att_dst  = (const float*)d_in[3];
    const float* bias_gat = (const float*)d_in[4];
    const float* W1       = (const float*)d_in[5];
    const float* b1       = (const float*)d_in[6];
    const float* W2       = (const float*)d_in[7];
    const float* b2       = (const float*)d_in[8];
    const float* n1w      = (const float*)d_in[9];
    const float* n2w      = (const float*)d_in[10];
    const void*  ei       = d_in[11];

    static int smem_set = 0;
    if (!smem_set) {
        cudaFuncSetAttribute(gemm_h, cudaFuncAttributeMaxDynamicSharedMemorySize, GSMEM);
        smem_set = 1;
    }

    __half *xh, *xph, *h1h, *Wg, *W1h, *W2h;
    cudaGetSymbolAddress((void**)&xh,  g_xh);
    cudaGetSymbolAddress((void**)&xph, g_xph);
    cudaGetSymbolAddress((void**)&h1h, g_h1h);
    cudaGetSymbolAddress((void**)&Wg,  g_Wg);
    cudaGetSymbolAddress((void**)&W1h, g_W1h);
    cudaGetSymbolAddress((void**)&W2h, g_W2h);

    k_setup<<<2500, 256>>>((const float4*)x, W_gat, W1, W2, (const unsigned*)ei);
    k_count<<<(EE / 2 + 255) / 256, 256>>>(ei);
    k_scan<<<1, 1024>>>();
    k_scatter<<<(EE / 2 + 255) / 256, 256>>>(ei);

    for (int i = 0; i < LL; i++) {
        gemm_h<<<dim3(HD / 128, MTILES), 256, GSMEM>>>(
            xh, Wg + (size_t)i * DD * HD, nullptr, xph, nullptr,
            att_src + i * HD, att_dst + i * HD, nullptr, HD, 0);
        k_agg<<<NV, 128>>>(bias_gat + i * DD, n1w + i * DD);
        gemm_h<<<dim3(1, MTILES), 256, GSMEM>>>(
            xh, W1h + (size_t)i * DD * DD, b1 + i * DD, h1h, nullptr,
            nullptr, nullptr, nullptr, DD, 1);
        gemm_h<<<dim3(1, MTILES), 256, GSMEM>>>(
            h1h, W2h + (size_t)i * DD * DD, b2 + i * DD, nullptr, n2w + i * DD,
            nullptr, nullptr, (i == LL - 1) ? (float*)d_out : nullptr, DD, 2);
    }
}

// round 5
// speedup vs baseline: 1.3660x; 1.3660x over previous
#include <cuda_runtime.h>
#include <cuda_fp16.h>
#include <mma.h>
using namespace nvcuda;

#define NV 20000
#define EE 320000
#define DD 128
#define HD 512
#define LL 3
#define MTILES 157
#define NV2 (MTILES * 128)
#define EPS_ 1.1920929e-07f

// ---------------- static device scratch ----------------
__device__ float  g_x  [NV2 * DD];
__device__ __half g_xh [NV2 * DD];
__device__ __half g_xph[(size_t)NV2 * HD];
__device__ __half g_h1h[NV2 * DD];
__device__ __half g_Wg [LL * DD * HD];
__device__ __half g_W1h[LL * DD * DD];
__device__ __half g_W2h[LL * DD * DD];
__device__ float  g_as[NV * 4];
__device__ float  g_ad[NV * 4];
__device__ int    g_rowptr[NV + 1];
__device__ int    g_deg[NV];
__device__ int    g_cursor[NV];
__device__ int    g_col[EE + NV];
__device__ int    g_is64;

// ---------------- fused setup ----------------
#define WHALF ((LL * DD * HD + 2 * LL * DD * DD) / 2)

__global__ void k_setup(const float4* __restrict__ x,
                        const float* __restrict__ Wg,
                        const float* __restrict__ W1,
                        const float* __restrict__ W2,
                        const unsigned* __restrict__ ei_w) {
    int i = blockIdx.x * 256 + threadIdx.x;
    if (i < NV * DD / 4) {
        float4 v = x[i];
        ((float4*)g_x)[i] = v;
        ((__half2*)g_xh)[i * 2]     = __floats2half2_rn(v.x, v.y);
        ((__half2*)g_xh)[i * 2 + 1] = __floats2half2_rn(v.z, v.w);
    }
    if (i < WHALF) {
        int j = i * 2;
        const float* src; __half* dst; int off;
        if (j < LL * DD * HD)                     { src = Wg; dst = g_Wg;  off = j; }
        else if (j < LL * DD * HD + LL * DD * DD) { src = W1; dst = g_W1h; off = j - LL * DD * HD; }
        else                                      { src = W2; dst = g_W2h; off = j - LL * DD * HD - LL * DD * DD; }
        float2 v = *(const float2*)(src + off);
        *(__half2*)(dst + off) = __floats2half2_rn(v.x, v.y);
    }
    if (i < NV) g_deg[i] = 1;
    if (blockIdx.x == 0) {
        __shared__ unsigned acc;
        if (threadIdx.x == 0) acc = 0u;
        __syncthreads();
        unsigned v = 0;
        for (int k = threadIdx.x; k < 2048; k += 256) v |= ei_w[2 * k + 1];
        if (v) atomicOr(&acc, 1u);
        __syncthreads();
        if (threadIdx.x == 0) g_is64 = (acc == 0u) ? 1 : 0;
    }
}

// ---------------- CSR build ----------------
__global__ void k_count(const void* ei) {
    int e = (blockIdx.x * 256 + threadIdx.x) * 2;
    if (e < EE) {
        int d0, d1;
        if (g_is64) {
            longlong2 v = ((const longlong2*)ei)[(EE + e) >> 1];
            d0 = (int)v.x; d1 = (int)v.y;
        } else {
            int2 v = ((const int2*)ei)[(EE + e) >> 1];
            d0 = v.x; d1 = v.y;
        }
        atomicAdd(&g_deg[d0], 1);
        atomicAdd(&g_deg[d1], 1);
    }
}

// scan + fill fused
__global__ __launch_bounds__(1024) void k_scan() {
    const int PER = 20;
    __shared__ int wsum[32];
    int t = threadIdx.x, lane = t & 31, w = t >> 5;
    int v[PER];
    int base = t * PER;
    int run = 0;
    if (base < NV) {
        const int4* p = (const int4*)(g_deg + base);
#pragma unroll
        for (int q = 0; q < 5; q++) {
            int4 d = p[q];
            run += d.x; v[q * 4 + 0] = run;
            run += d.y; v[q * 4 + 1] = run;
            run += d.z; v[q * 4 + 2] = run;
            run += d.w; v[q * 4 + 3] = run;
        }
    } else {
#pragma unroll
        for (int q = 0; q < PER; q++) v[q] = 0;
    }
    int tot = run, sc = tot;
#pragma unroll
    for (int o = 1; o < 32; o <<= 1) {
        int u = __shfl_up_sync(0xffffffffu, sc, o);
        if (lane >= o) sc += u;
    }
    if (lane == 31) wsum[w] = sc;
    __syncthreads();
    if (w == 0) {
        int s = wsum[lane];
#pragma unroll
        for (int o = 1; o < 32; o <<= 1) {
            int u = __shfl_up_sync(0xffffffffu, s, o);
            if (lane >= o) s += u;
        }
        wsum[lane] = s;
    }
    __syncthreads();
    int throff = ((w > 0) ? wsum[w - 1] : 0) + sc - tot;
    if (t == 0) g_rowptr[0] = 0;
    if (base < NV) {
#pragma unroll
        for (int q = 0; q < PER; q++) {
            int idx = base + q;
            int startq = throff + (q > 0 ? v[q - 1] : 0);
            g_rowptr[idx + 1] = throff + v[q];
            g_col[startq] = idx;        // self loop at slot 0
            g_cursor[idx] = startq + 1;
        }
    }
}
__global__ void k_scatter(const void* ei) {
    int e = (blockIdx.x * 256 + threadIdx.x) * 2;
    if (e < EE) {
        int s0, s1, d0, d1;
        if (g_is64) {
            longlong2 sv = ((const longlong2*)ei)[e >> 1];
            longlong2 dv = ((const longlong2*)ei)[(EE + e) >> 1];
            s0 = (int)sv.x; s1 = (int)sv.y; d0 = (int)dv.x; d1 = (int)dv.y;
        } else {
            int2 sv = ((const int2*)ei)[e >> 1];
            int2 dv = ((const int2*)ei)[(EE + e) >> 1];
            s0 = sv.x; s1 = sv.y; d0 = dv.x; d1 = dv.y;
        }
        g_col[atomicAdd(&g_cursor[d0], 1)] = s0;
        g_col[atomicAdd(&g_cursor[d1], 1)] = s1;
    }
}

// ---------------- fp16 tensor-core GEMM, K=128 smem resident (round-3 form) ----------------
// mode 0: write fp16 Ch
// mode 1: relu -> fp16 Ch
// mode 2: residual + RMSNorm; outF? write fp32 outF : write g_x + g_xh
#define GSMEM 78336

__global__ __launch_bounds__(256) void gemm_h(
    const __half* __restrict__ A, const __half* __restrict__ B,
    const float* __restrict__ bias, __half* __restrict__ Ch,
    const float* __restrict__ nw, float* __restrict__ outF,
    int Ncols, int mode)
{
    extern __shared__ char dsm[];
    __half* As = (__half*)dsm;
    __half* Bs = As + 128 * 136;
    float*  Brep = (float*)(dsm + 2 * 128 * 136 * 2);
    float*  stage = (float*)dsm;

    int bm = blockIdx.y * 128, bn = blockIdx.x * 128;
    int t = threadIdx.x, warp = t >> 5, lane = t & 31;
    int wr = warp & 1, wc = warp >> 1;

    for (int i = t; i < 16 * 128; i += 256) {
        int r = i >> 7, c = i & 127;
        Brep[r * 136 + c] = bias ? bias[bn + c] : 0.f;
    }
    __syncthreads();

    wmma::fragment<wmma::accumulator, 16, 16, 16, float> acc[4][2];
#pragma unroll
    for (int fr = 0; fr < 4; fr++)
#pragma unroll
        for (int fc = 0; fc < 2; fc++)
            wmma::load_matrix_sync(acc[fr][fc], &Brep[wc * 32 + fc * 16], 136,
                                   wmma::mem_row_major);

#pragma unroll
    for (int i = 0; i < 8; i++) {
        int idx = t + i * 256;
        int r = idx >> 4, c8 = (idx & 15) * 8;
        *(uint4*)(As + r * 136 + c8) = *(const uint4*)(A + (size_t)(bm + r) * 128 + c8);
        *(uint4*)(Bs + r * 136 + c8) = *(const uint4*)(B + (size_t)r * Ncols + bn + c8);
    }
    __syncthreads();

#pragma unroll
    for (int k = 0; k < 8; k++) {
        wmma::fragment<wmma::matrix_a, 16, 16, 16, __half, wmma::row_major> af[4];
        wmma::fragment<wmma::matrix_b, 16, 16, 16, __half, wmma::row_major> bf[2];
#pragma unroll
        for (int fr = 0; fr < 4; fr++)
            wmma::load_matrix_sync(af[fr], &As[(wr * 64 + fr * 16) * 136 + k * 16], 136);
#pragma unroll
        for (int fc = 0; fc < 2; fc++)
            wmma::load_matrix_sync(bf[fc], &Bs[(k * 16) * 136 + wc * 32 + fc * 16], 136);
#pragma unroll
        for (int fr = 0; fr < 4; fr++)
#pragma unroll
            for (int fc = 0; fc < 2; fc++)
                wmma::mma_sync(acc[fr][fc], af[fr], bf[fc], acc[fr][fc]);
    }
    __syncthreads();

    if (mode == 2) {
#pragma unroll
        for (int fr = 0; fr < 4; fr++)
#pragma unroll
            for (int fc = 0; fc < 2; fc++)
                wmma::store_matrix_sync(&stage[(wr * 64 + fr * 16) * 132 + wc * 32 + fc * 16],
                                        acc[fr][fc], 132, wmma::mem_row_major);
        __syncthreads();
        float4 nwv = *(const float4*)&nw[lane * 4];
        for (int r = warp; r < 128; r += 8) {
            size_t row = (size_t)(bm + r);
            float4 xr = *(const float4*)&g_x[row * 128 + lane * 4];
            float4 st = *(const float4*)&stage[r * 132 + lane * 4];
            float v0 = xr.x + st.x, v1 = xr.y + st.y, v2 = xr.z + st.z, v3 = xr.w + st.w;
            float ss = v0 * v0 + v1 * v1 + v2 * v2 + v3 * v3;
#pragma unroll
            for (int o = 16; o; o >>= 1) ss += __shfl_xor_sync(0xffffffffu, ss, o);
            float rr = rsqrtf(ss * (1.0f / DD) + EPS_);
            float o0 = v0 * rr * nwv.x, o1 = v1 * rr * nwv.y;
            float o2 = v2 * rr * nwv.z, o3 = v3 * rr * nwv.w;
            if (outF) {
                if (row < NV)
                    *(float4*)&outF[row * 128 + lane * 4] = make_float4(o0, o1, o2, o3);
            } else {
                *(float4*)&g_x[row * 128 + lane * 4] = make_float4(o0, o1, o2, o3);
                __half2 h0 = __floats2half2_rn(o0, o1);
                __half2 h1 = __floats2half2_rn(o2, o3);
                uint2 packed;
                packed.x = *(unsigned*)&h0;
                packed.y = *(unsigned*)&h1;
                *(uint2*)&g_xh[row * 128 + lane * 4] = packed;
            }
        }
    } else {
        if (mode == 1) {
#pragma unroll
            for (int fr = 0; fr < 4; fr++)
#pragma unroll
                for (int fc = 0; fc < 2; fc++)
#pragma unroll
                    for (int i = 0; i < acc[fr][fc].num_elements; i++)
                        acc[fr][fc].x[i] = fmaxf(acc[fr][fc].x[i], 0.f);
        }
        float* ws = stage + warp * 2304;  // 64x36 per warp
#pragma unroll
        for (int fr = 0; fr < 4; fr++)
#pragma unroll
            for (int fc = 0; fc < 2; fc++)
                wmma::store_matrix_sync(&ws[fr * 16 * 36 + fc * 16], acc[fr][fc], 36,
                                        wmma::mem_row_major);
        __syncwarp();
        // vectorized fp16 store: 4 cols per op
        for (int i = lane; i < 64 * 8; i += 32) {
            int r = i >> 3, c4 = (i & 7) * 4;
            __half2 h0 = __floats2half2_rn(ws[r * 36 + c4], ws[r * 36 + c4 + 1]);
            __half2 h1 = __floats2half2_rn(ws[r * 36 + c4 + 2], ws[r * 36 + c4 + 3]);
            uint2 packed;
            packed.x = *(unsigned*)&h0;
            packed.y = *(unsigned*)&h1;
            *(uint2*)(Ch + (size_t)(bm + wr * 64 + r) * Ncols + bn + wc * 32 + c4) = packed;
        }
    }
}

// ---------------- attention dots (fp16 xp) ----------------
__global__ __launch_bounds__(128) void k_dots(const float* __restrict__ att_s,
                                              const float* __restrict__ att_d) {
    int warp = threadIdx.x >> 5, lane = threadIdx.x & 31;
    int n = blockIdx.x * 4 + warp;
    if (n >= NV) return;
    const __half* xpr = g_xph + (size_t)n * HD;
#pragma unroll
    for (int h = 0; h < 4; h++) {
        uint2 raw = *(const uint2*)(xpr + h * 128 + lane * 4);
        float2 f0 = __half22float2(*(__half2*)&raw.x);
        float2 f1 = __half22float2(*(__half2*)&raw.y);
        float4 as = *(const float4*)&att_s[h * 128 + lane * 4];
        float4 ad = *(const float4*)&att_d[h * 128 + lane * 4];
        float ps = f0.x * as.x + f0.y * as.y + f1.x * as.z + f1.y * as.w;
        float pd = f0.x * ad.x + f0.y * ad.y + f1.x * ad.z + f1.y * ad.w;
#pragma unroll
        for (int o = 16; o; o >>= 1) {
            ps += __shfl_xor_sync(0xffffffffu, ps, o);
            pd += __shfl_xor_sync(0xffffffffu, pd, o);
        }
        if (lane == 0) {
            g_as[n * 4 + h] = ps;
            g_ad[n * 4 + h] = pd;
        }
    }
}

__device__ __forceinline__ float lrelu(float x) { return x > 0.f ? x : 0.2f * x; }

__device__ __forceinline__ void comb(float& m, float& s, float m2, float s2) {
    float M = fmaxf(m, m2);
    s = s * __expf(m - M) + s2 * __expf(m2 - M);
    m = M;
}

// ---------------- fused GAT aggregation (round-3 online form) ----------------
__global__ __launch_bounds__(128) void k_agg(const float* __restrict__ bias,
                                             const float* __restrict__ nw) {
    int n = blockIdx.x, t = threadIdx.x;
    int start = g_rowptr[n];
    int deg = g_rowptr[n + 1] - start;

    __shared__ float smm[4][4], sms[4][4];
    __shared__ float sh_alpha[128][4];
    __shared__ int sh_src[128];
    __shared__ float xatt[4][128];
    __shared__ float shred[128];

    float4 adv = *(const float4*)&g_ad[n * 4];

    // online pass: per-head (max, sum)
    float m[4] = {-1e30f, -1e30f, -1e30f, -1e30f};
    float s[4] = {0.f, 0.f, 0.f, 0.f};
    for (int j = t; j < deg; j += 128) {
        int src = g_col[start + j];
        float4 asv = *(const float4*)&g_as[src * 4];
        float e[4] = {lrelu(asv.x + adv.x), lrelu(asv.y + adv.y),
                      lrelu(asv.z + adv.z), lrelu(asv.w + adv.w)};
#pragma unroll
        for (int h = 0; h < 4; h++) comb(m[h], s[h], e[h], 1.f);
    }
    int lane = t & 31, w = t >> 5;
#pragma unroll
    for (int h = 0; h < 4; h++) {
#pragma unroll
        for (int o = 16; o; o >>= 1) {
            float m2 = __shfl_xor_sync(0xffffffffu, m[h], o);
            float s2 = __shfl_xor_sync(0xffffffffu, s[h], o);
            comb(m[h], s[h], m2, s2);
        }
        if (lane == 0) { smm[w][h] = m[h]; sms[w][h] = s[h]; }
    }
    __syncthreads();
    float M[4], inv[4];
#pragma unroll
    for (int h = 0; h < 4; h++) {
        float Mx = fmaxf(fmaxf(smm[0][h], smm[1][h]), fmaxf(smm[2][h], smm[3][h]));
        float S = sms[0][h] * __expf(smm[0][h] - Mx) + sms[1][h] * __expf(smm[1][h] - Mx)
                + sms[2][h] * __expf(smm[2][h] - Mx) + sms[3][h] * __expf(smm[3][h] - Mx);
        M[h] = Mx;
        inv[h] = 1.f / S;
    }

    // gather pass: thread owns (head h, quad q) -> 4 dims (fp16 loads)
    int h = t >> 5, q = t & 31;
    float4 acc4 = make_float4(0.f, 0.f, 0.f, 0.f);
    for (int c0 = 0; c0 < deg; c0 += 128) {
        int j = c0 + t;
        if (j < deg) {
            int src = g_col[start + j];
            sh_src[t] = src;
            float4 asv = *(const float4*)&g_as[src * 4];
            sh_alpha[t][0] = __expf(lrelu(asv.x + adv.x) - M[0]) * inv[0];
            sh_alpha[t][1] = __expf(lrelu(asv.y + adv.y) - M[1]) * inv[1];
            sh_alpha[t][2] = __expf(lrelu(asv.z + adv.z) - M[2]) * inv[2];
            sh_alpha[t][3] = __expf(lrelu(asv.w + adv.w) - M[3]) * inv[3];
        }
        __syncthreads();
        int cnt = min(128, deg - c0);
        for (int jj = 0; jj < cnt; jj++) {
            float al = sh_alpha[jj][h];
            uint2 raw = *(const uint2*)(g_xph + (size_t)sh_src[jj] * HD + h * 128 + q * 4);
            float2 f0 = __half22float2(*(__half2*)&raw.x);
            float2 f1 = __half22float2(*(__half2*)&raw.y);
            acc4.x += al * f0.x;
            acc4.y += al * f0.y;
            acc4.z += al * f1.x;
            acc4.w += al * f1.y;
        }
        __syncthreads();
    }
    *(float4*)&xatt[h][q * 4] = acc4;
    __syncthreads();

    float a = 0.25f * (xatt[0][t] + xatt[1][t] + xatt[2][t] + xatt[3][t]);
    float v = g_x[n * DD + t] + a + bias[t];
    shred[t] = v * v;
    __syncthreads();
#pragma unroll
    for (int o = 64; o; o >>= 1) {
        if (t < o) shred[t] += shred[t + o];
        __syncthreads();
    }
    float r = rsqrtf(shred[0] * (1.0f / DD) + EPS_);
    float o = v * r * nw[t];
    g_x[n * DD + t] = o;
    g_xh[n * DD + t] = __float2half(o);
}

// ---------------- host ----------------
extern "C" void kernel_launch(void* const* d_in, const int* in_sizes, int n_in,
                              void* d_out, int out_size) {
    const float* x        = (const float*)d_in[0];
    const float* W_gat    = (const float*)d_in[1];
    const float* att_src  = (const float*)d_in[2];
    const float* att_dst  = (const float*)d_in[3];
    const float* bias_gat = (const float*)d_in[4];
    const float* W1       = (const float*)d_in[5];
    const float* b1       = (const float*)d_in[6];
    const float* W2       = (const float*)d_in[7];
    const float* b2       = (const float*)d_in[8];
    const float* n1w      = (const float*)d_in[9];
    const float* n2w      = (const float*)d_in[10];
    const void*  ei       = d_in[11];

    static int smem_set = 0;
    if (!smem_set) {
        cudaFuncSetAttribute(gemm_h, cudaFuncAttributeMaxDynamicSharedMemorySize, GSMEM);
        smem_set = 1;
    }

    __half *xh, *xph, *h1h, *Wg, *W1h, *W2h;
    cudaGetSymbolAddress((void**)&xh,  g_xh);
    cudaGetSymbolAddress((void**)&xph, g_xph);
    cudaGetSymbolAddress((void**)&h1h, g_h1h);
    cudaGetSymbolAddress((void**)&Wg,  g_Wg);
    cudaGetSymbolAddress((void**)&W1h, g_W1h);
    cudaGetSymbolAddress((void**)&W2h, g_W2h);

    k_setup<<<2500, 256>>>((const float4*)x, W_gat, W1, W2, (const unsigned*)ei);
    k_count<<<(EE / 2 + 255) / 256, 256>>>(ei);
    k_scan<<<1, 1024>>>();
    k_scatter<<<(EE / 2 + 255) / 256, 256>>>(ei);

    for (int i = 0; i < LL; i++) {
        gemm_h<<<dim3(HD / 128, MTILES), 256, GSMEM>>>(
            xh, Wg + (size_t)i * DD * HD, nullptr, xph, nullptr, nullptr, HD, 0);
        k_dots<<<(NV + 3) / 4, 128>>>(att_src + i * HD, att_dst + i * HD);
        k_agg<<<NV, 128>>>(bias_gat + i * DD, n1w + i * DD);
        gemm_h<<<dim3(1, MTILES), 256, GSMEM>>>(
            xh, W1h + (size_t)i * DD * DD, b1 + i * DD, h1h, nullptr, nullptr, DD, 1);
        gemm_h<<<dim3(1, MTILES), 256, GSMEM>>>(
            h1h, W2h + (size_t)i * DD * DD, b2 + i * DD, nullptr, n2w + i * DD,
            (i == LL - 1) ? (float*)d_out : nullptr, DD, 2);
    }
}

// round 6
// speedup vs baseline: 1.4013x; 1.0258x over previous
#include <cuda_runtime.h>
#include <cuda_fp16.h>
#include <mma.h>
using namespace nvcuda;

#define NV 20000
#define EE 320000
#define DD 128
#define HD 512
#define LL 3
#define MTILES 157
#define NV2 (MTILES * 128)
#define EPS_ 1.1920929e-07f

// ---------------- static device scratch ----------------
__device__ float  g_x  [NV2 * DD];
__device__ __half g_xh [NV2 * DD];
__device__ __half g_xph[(size_t)NV2 * HD];
__device__ __half g_Wg [LL * DD * HD];
__device__ __half g_W1h[LL * DD * DD];
__device__ __half g_W2h[LL * DD * DD];
__device__ float  g_as[NV * 4];
__device__ float  g_ad[NV * 4];
__device__ int    g_rowptr[NV + 1];
__device__ int    g_deg[NV];
__device__ int    g_cursor[NV];
__device__ int    g_col[EE + NV];
__device__ int    g_is64;

// ---------------- fused setup ----------------
#define WHALF ((LL * DD * HD + 2 * LL * DD * DD) / 2)

__global__ void k_setup(const float4* __restrict__ x,
                        const float* __restrict__ Wg,
                        const float* __restrict__ W1,
                        const float* __restrict__ W2,
                        const unsigned* __restrict__ ei_w) {
    int i = blockIdx.x * 256 + threadIdx.x;
    if (i < NV * DD / 4) {
        float4 v = x[i];
        ((float4*)g_x)[i] = v;
        ((__half2*)g_xh)[i * 2]     = __floats2half2_rn(v.x, v.y);
        ((__half2*)g_xh)[i * 2 + 1] = __floats2half2_rn(v.z, v.w);
    }
    if (i < WHALF) {
        int j = i * 2;
        const float* src; __half* dst; int off;
        if (j < LL * DD * HD)                     { src = Wg; dst = g_Wg;  off = j; }
        else if (j < LL * DD * HD + LL * DD * DD) { src = W1; dst = g_W1h; off = j - LL * DD * HD; }
        else                                      { src = W2; dst = g_W2h; off = j - LL * DD * HD - LL * DD * DD; }
        float2 v = *(const float2*)(src + off);
        *(__half2*)(dst + off) = __floats2half2_rn(v.x, v.y);
    }
    if (i < NV) g_deg[i] = 1;
    if (blockIdx.x == 0) {
        __shared__ unsigned acc;
        if (threadIdx.x == 0) acc = 0u;
        __syncthreads();
        unsigned v = 0;
        for (int k = threadIdx.x; k < 2048; k += 256) v |= ei_w[2 * k + 1];
        if (v) atomicOr(&acc, 1u);
        __syncthreads();
        if (threadIdx.x == 0) g_is64 = (acc == 0u) ? 1 : 0;
    }
}

// ---------------- CSR build ----------------
__global__ void k_count(const void* ei) {
    int e = (blockIdx.x * 256 + threadIdx.x) * 2;
    if (e < EE) {
        int d0, d1;
        if (g_is64) {
            longlong2 v = ((const longlong2*)ei)[(EE + e) >> 1];
            d0 = (int)v.x; d1 = (int)v.y;
        } else {
            int2 v = ((const int2*)ei)[(EE + e) >> 1];
            d0 = v.x; d1 = v.y;
        }
        atomicAdd(&g_deg[d0], 1);
        atomicAdd(&g_deg[d1], 1);
    }
}

__global__ __launch_bounds__(1024) void k_scan() {
    const int PER = 20;
    __shared__ int wsum[32];
    int t = threadIdx.x, lane = t & 31, w = t >> 5;
    int v[PER];
    int base = t * PER;
    int run = 0;
    if (base < NV) {
        const int4* p = (const int4*)(g_deg + base);
#pragma unroll
        for (int q = 0; q < 5; q++) {
            int4 d = p[q];
            run += d.x; v[q * 4 + 0] = run;
            run += d.y; v[q * 4 + 1] = run;
            run += d.z; v[q * 4 + 2] = run;
            run += d.w; v[q * 4 + 3] = run;
        }
    } else {
#pragma unroll
        for (int q = 0; q < PER; q++) v[q] = 0;
    }
    int tot = run, sc = tot;
#pragma unroll
    for (int o = 1; o < 32; o <<= 1) {
        int u = __shfl_up_sync(0xffffffffu, sc, o);
        if (lane >= o) sc += u;
    }
    if (lane == 31) wsum[w] = sc;
    __syncthreads();
    if (w == 0) {
        int s = wsum[lane];
#pragma unroll
        for (int o = 1; o < 32; o <<= 1) {
            int u = __shfl_up_sync(0xffffffffu, s, o);
            if (lane >= o) s += u;
        }
        wsum[lane] = s;
    }
    __syncthreads();
    int throff = ((w > 0) ? wsum[w - 1] : 0) + sc - tot;
    if (t == 0) g_rowptr[0] = 0;
    if (base < NV) {
#pragma unroll
        for (int q = 0; q < PER; q++) {
            int idx = base + q;
            int startq = throff + (q > 0 ? v[q - 1] : 0);
            g_rowptr[idx + 1] = throff + v[q];
            g_col[startq] = idx;        // self loop at slot 0
            g_cursor[idx] = startq + 1;
        }
    }
}
__global__ void k_scatter(const void* ei) {
    int e = (blockIdx.x * 256 + threadIdx.x) * 2;
    if (e < EE) {
        int s0, s1, d0, d1;
        if (g_is64) {
            longlong2 sv = ((const longlong2*)ei)[e >> 1];
            longlong2 dv = ((const longlong2*)ei)[(EE + e) >> 1];
            s0 = (int)sv.x; s1 = (int)sv.y; d0 = (int)dv.x; d1 = (int)dv.y;
        } else {
            int2 sv = ((const int2*)ei)[e >> 1];
            int2 dv = ((const int2*)ei)[(EE + e) >> 1];
            s0 = sv.x; s1 = sv.y; d0 = dv.x; d1 = dv.y;
        }
        g_col[atomicAdd(&g_cursor[d0], 1)] = s0;
        g_col[atomicAdd(&g_cursor[d1], 1)] = s1;
    }
}

// ---------------- fp16 tensor-core GEMM for xp (mode-0 only now) ----------------
#define GSMEM 78336

__global__ __launch_bounds__(256) void gemm_h(
    const __half* __restrict__ A, const __half* __restrict__ B,
    __half* __restrict__ Ch, int Ncols)
{
    extern __shared__ char dsm[];
    __half* As = (__half*)dsm;
    __half* Bs = As + 128 * 136;
    float*  stage = (float*)dsm;

    int bm = blockIdx.y * 128, bn = blockIdx.x * 128;
    int t = threadIdx.x, warp = t >> 5, lane = t & 31;
    int wr = warp & 1, wc = warp >> 1;

    wmma::fragment<wmma::accumulator, 16, 16, 16, float> acc[4][2];
#pragma unroll
    for (int fr = 0; fr < 4; fr++)
#pragma unroll
        for (int fc = 0; fc < 2; fc++)
            wmma::fill_fragment(acc[fr][fc], 0.f);

#pragma unroll
    for (int i = 0; i < 8; i++) {
        int idx = t + i * 256;
        int r = idx >> 4, c8 = (idx & 15) * 8;
        *(uint4*)(As + r * 136 + c8) = *(const uint4*)(A + (size_t)(bm + r) * 128 + c8);
        *(uint4*)(Bs + r * 136 + c8) = *(const uint4*)(B + (size_t)r * Ncols + bn + c8);
    }
    __syncthreads();

#pragma unroll
    for (int k = 0; k < 8; k++) {
        wmma::fragment<wmma::matrix_a, 16, 16, 16, __half, wmma::row_major> af[4];
        wmma::fragment<wmma::matrix_b, 16, 16, 16, __half, wmma::row_major> bf[2];
#pragma unroll
        for (int fr = 0; fr < 4; fr++)
            wmma::load_matrix_sync(af[fr], &As[(wr * 64 + fr * 16) * 136 + k * 16], 136);
#pragma unroll
        for (int fc = 0; fc < 2; fc++)
            wmma::load_matrix_sync(bf[fc], &Bs[(k * 16) * 136 + wc * 32 + fc * 16], 136);
#pragma unroll
        for (int fr = 0; fr < 4; fr++)
#pragma unroll
            for (int fc = 0; fc < 2; fc++)
                wmma::mma_sync(acc[fr][fc], af[fr], bf[fc], acc[fr][fc]);
    }
    __syncthreads();

    float* ws = stage + warp * 2304;  // 64x36 per warp
#pragma unroll
    for (int fr = 0; fr < 4; fr++)
#pragma unroll
        for (int fc = 0; fc < 2; fc++)
            wmma::store_matrix_sync(&ws[fr * 16 * 36 + fc * 16], acc[fr][fc], 36,
                                    wmma::mem_row_major);
    __syncwarp();
    for (int i = lane; i < 64 * 8; i += 32) {
        int r = i >> 3, c4 = (i & 7) * 4;
        __half2 h0 = __floats2half2_rn(ws[r * 36 + c4], ws[r * 36 + c4 + 1]);
        __half2 h1 = __floats2half2_rn(ws[r * 36 + c4 + 2], ws[r * 36 + c4 + 3]);
        uint2 packed;
        packed.x = *(unsigned*)&h0;
        packed.y = *(unsigned*)&h1;
        *(uint2*)(Ch + (size_t)(bm + wr * 64 + r) * Ncols + bn + wc * 32 + c4) = packed;
    }
}

// ---------------- fused FFN: relu(A@W1+b1)@W2 + b2 -> residual + RMSNorm ----------------
// smem: region0 = As(128x136 h) | Ws(128x136 h)  [= stage float 128x132 later]
//       region1 = Hs(128x136 h); Brep(16x136 f) aliases Hs before MMA1
#define FSMEM (69632 + 34816)

__global__ __launch_bounds__(256) void k_ffn(
    const __half* __restrict__ W1, const __half* __restrict__ W2,
    const float* __restrict__ b1, const float* __restrict__ b2,
    const float* __restrict__ nw, float* __restrict__ outF)
{
    extern __shared__ char dsm[];
    __half* As = (__half*)dsm;
    __half* Ws = As + 128 * 136;
    float*  stage = (float*)dsm;
    __half* Hs = (__half*)(dsm + 69632);
    float*  Brep = (float*)(dsm + 69632);

    int bm = blockIdx.x * 128;
    int t = threadIdx.x, warp = t >> 5, lane = t & 31;
    int wr = warp & 1, wc = warp >> 1;

    // stage loads: A tile, W1, bias-replica
    for (int i = t; i < 16 * 128; i += 256) {
        int r = i >> 7, c = i & 127;
        Brep[r * 136 + c] = b1[c];
    }
#pragma unroll
    for (int i = 0; i < 8; i++) {
        int idx = t + i * 256;
        int r = idx >> 4, c8 = (idx & 15) * 8;
        *(uint4*)(As + r * 136 + c8) = *(const uint4*)(g_xh + (size_t)(bm + r) * 128 + c8);
        *(uint4*)(Ws + r * 136 + c8) = *(const uint4*)(W1 + (size_t)r * 128 + c8);
    }
    __syncthreads();

    wmma::fragment<wmma::accumulator, 16, 16, 16, float> acc[4][2];
#pragma unroll
    for (int fr = 0; fr < 4; fr++)
#pragma unroll
        for (int fc = 0; fc < 2; fc++)
            wmma::load_matrix_sync(acc[fr][fc], &Brep[wc * 32 + fc * 16], 136,
                                   wmma::mem_row_major);

#pragma unroll
    for (int k = 0; k < 8; k++) {
        wmma::fragment<wmma::matrix_a, 16, 16, 16, __half, wmma::row_major> af[4];
        wmma::fragment<wmma::matrix_b, 16, 16, 16, __half, wmma::row_major> bf[2];
#pragma unroll
        for (int fr = 0; fr < 4; fr++)
            wmma::load_matrix_sync(af[fr], &As[(wr * 64 + fr * 16) * 136 + k * 16], 136);
#pragma unroll
        for (int fc = 0; fc < 2; fc++)
            wmma::load_matrix_sync(bf[fc], &Ws[(k * 16) * 136 + wc * 32 + fc * 16], 136);
#pragma unroll
        for (int fr = 0; fr < 4; fr++)
#pragma unroll
            for (int fc = 0; fc < 2; fc++)
                wmma::mma_sync(acc[fr][fc], af[fr], bf[fc], acc[fr][fc]);
    }
    __syncthreads();  // As/Ws consumed

    // relu on fragments, stage full tile as f32
#pragma unroll
    for (int fr = 0; fr < 4; fr++)
#pragma unroll
        for (int fc = 0; fc < 2; fc++) {
#pragma unroll
            for (int i = 0; i < acc[fr][fc].num_elements; i++)
                acc[fr][fc].x[i] = fmaxf(acc[fr][fc].x[i], 0.f);
            wmma::store_matrix_sync(&stage[(wr * 64 + fr * 16) * 132 + wc * 32 + fc * 16],
                                    acc[fr][fc], 132, wmma::mem_row_major);
        }
    __syncthreads();

    // convert h tile -> fp16 Hs (overwrites Brep region; Brep no longer needed)
    for (int i = t; i < 128 * 32; i += 256) {
        int r = i >> 5, c4 = (i & 31) * 4;
        float4 v = *(const float4*)&stage[r * 132 + c4];
        __half2 h0 = __floats2half2_rn(v.x, v.y);
        __half2 h1 = __floats2half2_rn(v.z, v.w);
        uint2 packed;
        packed.x = *(unsigned*)&h0;
        packed.y = *(unsigned*)&h1;
        *(uint2*)(Hs + r * 136 + c4) = packed;
    }
    __syncthreads();

    // load W2 into region0 (overwrites stage)
#pragma unroll
    for (int i = 0; i < 8; i++) {
        int idx = t + i * 256;
        int r = idx >> 4, c8 = (idx & 15) * 8;
        *(uint4*)(As + r * 136 + c8) = *(const uint4*)(W2 + (size_t)r * 128 + c8);
    }
    __syncthreads();

#pragma unroll
    for (int fr = 0; fr < 4; fr++)
#pragma unroll
        for (int fc = 0; fc < 2; fc++)
            wmma::fill_fragment(acc[fr][fc], 0.f);

#pragma unroll
    for (int k = 0; k < 8; k++) {
        wmma::fragment<wmma::matrix_a, 16, 16, 16, __half, wmma::row_major> af[4];
        wmma::fragment<wmma::matrix_b, 16, 16, 16, __half, wmma::row_major> bf[2];
#pragma unroll
        for (int fr = 0; fr < 4; fr++)
            wmma::load_matrix_sync(af[fr], &Hs[(wr * 64 + fr * 16) * 136 + k * 16], 136);
#pragma unroll
        for (int fc = 0; fc < 2; fc++)
            wmma::load_matrix_sync(bf[fc], &As[(k * 16) * 136 + wc * 32 + fc * 16], 136);
#pragma unroll
        for (int fr = 0; fr < 4; fr++)
#pragma unroll
            for (int fc = 0; fc < 2; fc++)
                wmma::mma_sync(acc[fr][fc], af[fr], bf[fc], acc[fr][fc]);
    }
    __syncthreads();  // As(W2) consumed

#pragma unroll
    for (int fr = 0; fr < 4; fr++)
#pragma unroll
        for (int fc = 0; fc < 2; fc++)
            wmma::store_matrix_sync(&stage[(wr * 64 + fr * 16) * 132 + wc * 32 + fc * 16],
                                    acc[fr][fc], 132, wmma::mem_row_major);
    __syncthreads();

    // epilogue: v = x + h2 + b2, RMSNorm
    float4 nwv = *(const float4*)&nw[lane * 4];
    float4 b2v = *(const float4*)&b2[lane * 4];
    for (int r = warp; r < 128; r += 8) {
        size_t row = (size_t)(bm + r);
        float4 xr = *(const float4*)&g_x[row * 128 + lane * 4];
        float4 st = *(const float4*)&stage[r * 132 + lane * 4];
        float v0 = xr.x + st.x + b2v.x, v1 = xr.y + st.y + b2v.y;
        float v2 = xr.z + st.z + b2v.z, v3 = xr.w + st.w + b2v.w;
        float ss = v0 * v0 + v1 * v1 + v2 * v2 + v3 * v3;
#pragma unroll
        for (int o = 16; o; o >>= 1) ss += __shfl_xor_sync(0xffffffffu, ss, o);
        float rr = rsqrtf(ss * (1.0f / DD) + EPS_);
        float o0 = v0 * rr * nwv.x, o1 = v1 * rr * nwv.y;
        float o2 = v2 * rr * nwv.z, o3 = v3 * rr * nwv.w;
        if (outF) {
            if (row < NV)
                *(float4*)&outF[row * 128 + lane * 4] = make_float4(o0, o1, o2, o3);
        } else {
            *(float4*)&g_x[row * 128 + lane * 4] = make_float4(o0, o1, o2, o3);
            __half2 h0 = __floats2half2_rn(o0, o1);
            __half2 h1 = __floats2half2_rn(o2, o3);
            uint2 packed;
            packed.x = *(unsigned*)&h0;
            packed.y = *(unsigned*)&h1;
            *(uint2*)&g_xh[row * 128 + lane * 4] = packed;
        }
    }
}

// ---------------- attention dots (fp16 xp) ----------------
__global__ __launch_bounds__(128) void k_dots(const float* __restrict__ att_s,
                                              const float* __restrict__ att_d) {
    int warp = threadIdx.x >> 5, lane = threadIdx.x & 31;
    int n = blockIdx.x * 4 + warp;
    if (n >= NV) return;
    const __half* xpr = g_xph + (size_t)n * HD;
#pragma unroll
    for (int h = 0; h < 4; h++) {
        uint2 raw = *(const uint2*)(xpr + h * 128 + lane * 4);
        float2 f0 = __half22float2(*(__half2*)&raw.x);
        float2 f1 = __half22float2(*(__half2*)&raw.y);
        float4 as = *(const float4*)&att_s[h * 128 + lane * 4];
        float4 ad = *(const float4*)&att_d[h * 128 + lane * 4];
        float ps = f0.x * as.x + f0.y * as.y + f1.x * as.z + f1.y * as.w;
        float pd = f0.x * ad.x + f0.y * ad.y + f1.x * ad.z + f1.y * ad.w;
#pragma unroll
        for (int o = 16; o; o >>= 1) {
            ps += __shfl_xor_sync(0xffffffffu, ps, o);
            pd += __shfl_xor_sync(0xffffffffu, pd, o);
        }
        if (lane == 0) {
            g_as[n * 4 + h] = ps;
            g_ad[n * 4 + h] = pd;
        }
    }
}

__device__ __forceinline__ float lrelu(float x) { return x > 0.f ? x : 0.2f * x; }

__device__ __forceinline__ void comb(float& m, float& s, float m2, float s2) {
    float M = fmaxf(m, m2);
    s = s * __expf(m - M) + s2 * __expf(m2 - M);
    m = M;
}

// ---------------- fused GAT aggregation ----------------
__global__ __launch_bounds__(128) void k_agg(const float* __restrict__ bias,
                                             const float* __restrict__ nw) {
    int n = blockIdx.x, t = threadIdx.x;
    int start = g_rowptr[n];
    int deg = g_rowptr[n + 1] - start;

    __shared__ float smm[4][4], sms[4][4];
    __shared__ float sh_alpha[128][4];
    __shared__ int sh_src[128];
    __shared__ float xatt[4][128];
    __shared__ float shred[128];

    float4 adv = *(const float4*)&g_ad[n * 4];

    float m[4] = {-1e30f, -1e30f, -1e30f, -1e30f};
    float s[4] = {0.f, 0.f, 0.f, 0.f};
    for (int j = t; j < deg; j += 128) {
        int src = g_col[start + j];
        float4 asv = *(const float4*)&g_as[src * 4];
        float e[4] = {lrelu(asv.x + adv.x), lrelu(asv.y + adv.y),
                      lrelu(asv.z + adv.z), lrelu(asv.w + adv.w)};
#pragma unroll
        for (int h = 0; h < 4; h++) comb(m[h], s[h], e[h], 1.f);
    }
    int lane = t & 31, w = t >> 5;
#pragma unroll
    for (int h = 0; h < 4; h++) {
#pragma unroll
        for (int o = 16; o; o >>= 1) {
            float m2 = __shfl_xor_sync(0xffffffffu, m[h], o);
            float s2 = __shfl_xor_sync(0xffffffffu, s[h], o);
            comb(m[h], s[h], m2, s2);
        }
        if (lane == 0) { smm[w][h] = m[h]; sms[w][h] = s[h]; }
    }
    __syncthreads();
    float M[4], inv[4];
#pragma unroll
    for (int h = 0; h < 4; h++) {
        float Mx = fmaxf(fmaxf(smm[0][h], smm[1][h]), fmaxf(smm[2][h], smm[3][h]));
        float S = sms[0][h] * __expf(smm[0][h] - Mx) + sms[1][h] * __expf(smm[1][h] - Mx)
                + sms[2][h] * __expf(smm[2][h] - Mx) + sms[3][h] * __expf(smm[3][h] - Mx);
        M[h] = Mx;
        inv[h] = 1.f / S;
    }

    int h = t >> 5, q = t & 31;
    float4 acc4 = make_float4(0.f, 0.f, 0.f, 0.f);
    for (int c0 = 0; c0 < deg; c0 += 128) {
        int j = c0 + t;
        if (j < deg) {
            int src = g_col[start + j];
            sh_src[t] = src;
            float4 asv = *(const float4*)&g_as[src * 4];
            sh_alpha[t][0] = __expf(lrelu(asv.x + adv.x) - M[0]) * inv[0];
            sh_alpha[t][1] = __expf(lrelu(asv.y + adv.y) - M[1]) * inv[1];
            sh_alpha[t][2] = __expf(lrelu(asv.z + adv.z) - M[2]) * inv[2];
            sh_alpha[t][3] = __expf(lrelu(asv.w + adv.w) - M[3]) * inv[3];
        }
        __syncthreads();
        int cnt = min(128, deg - c0);
        for (int jj = 0; jj < cnt; jj++) {
            float al = sh_alpha[jj][h];
            uint2 raw = *(const uint2*)(g_xph + (size_t)sh_src[jj] * HD + h * 128 + q * 4);
            float2 f0 = __half22float2(*(__half2*)&raw.x);
            float2 f1 = __half22float2(*(__half2*)&raw.y);
            acc4.x += al * f0.x;
            acc4.y += al * f0.y;
            acc4.z += al * f1.x;
            acc4.w += al * f1.y;
        }
        __syncthreads();
    }
    *(float4*)&xatt[h][q * 4] = acc4;
    __syncthreads();

    float a = 0.25f * (xatt[0][t] + xatt[1][t] + xatt[2][t] + xatt[3][t]);
    float v = g_x[n * DD + t] + a + bias[t];
    shred[t] = v * v;
    __syncthreads();
#pragma unroll
    for (int o = 64; o; o >>= 1) {
        if (t < o) shred[t] += shred[t + o];
        __syncthreads();
    }
    float r = rsqrtf(shred[0] * (1.0f / DD) + EPS_);
    float o = v * r * nw[t];
    g_x[n * DD + t] = o;
    g_xh[n * DD + t] = __float2half(o);
}

// ---------------- host ----------------
extern "C" void kernel_launch(void* const* d_in, const int* in_sizes, int n_in,
                              void* d_out, int out_size) {
    const float* x        = (const float*)d_in[0];
    const float* W_gat    = (const float*)d_in[1];
    const float* att_src  = (const float*)d_in[2];
    const float* att_dst  = (const float*)d_in[3];
    const float* bias_gat = (const float*)d_in[4];
    const float* W1       = (const float*)d_in[5];
    const float* b1       = (const float*)d_in[6];
    const float* W2       = (const float*)d_in[7];
    const float* b2       = (const float*)d_in[8];
    const float* n1w      = (const float*)d_in[9];
    const float* n2w      = (const float*)d_in[10];
    const void*  ei       = d_in[11];

    static int smem_set = 0;
    if (!smem_set) {
        cudaFuncSetAttribute(gemm_h, cudaFuncAttributeMaxDynamicSharedMemorySize, GSMEM);
        cudaFuncSetAttribute(k_ffn, cudaFuncAttributeMaxDynamicSharedMemorySize, FSMEM);
        smem_set = 1;
    }

    __half *xh, *xph, *Wg, *W1h, *W2h;
    cudaGetSymbolAddress((void**)&xh,  g_xh);
    cudaGetSymbolAddress((void**)&xph, g_xph);
    cudaGetSymbolAddress((void**)&Wg,  g_Wg);
    cudaGetSymbolAddress((void**)&W1h, g_W1h);
    cudaGetSymbolAddress((void**)&W2h, g_W2h);

    k_setup<<<2500, 256>>>((const float4*)x, W_gat, W1, W2, (const unsigned*)ei);
    k_count<<<(EE / 2 + 255) / 256, 256>>>(ei);
    k_scan<<<1, 1024>>>();
    k_scatter<<<(EE / 2 + 255) / 256, 256>>>(ei);

    for (int i = 0; i < LL; i++) {
        gemm_h<<<dim3(HD / 128, MTILES), 256, GSMEM>>>(
            xh, Wg + (size_t)i * DD * HD, xph, HD);
        k_dots<<<(NV + 3) / 4, 128>>>(att_src + i * HD, att_dst + i * HD);
        k_agg<<<NV, 128>>>(bias_gat + i * DD, n1w + i * DD);
        k_ffn<<<MTILES, 256, FSMEM>>>(
            W1h + (size_t)i * DD * DD, W2h + (size_t)i * DD * DD,
            b1 + i * DD, b2 + i * DD, n2w + i * DD,
            (i == LL - 1) ? (float*)d_out : nullptr);
    }
}

// round 7
// speedup vs baseline: 1.7840x; 1.2731x over previous
#include <cuda_runtime.h>
#include <cuda_fp16.h>
#include <mma.h>
using namespace nvcuda;

#define NV 20000
#define EE 320000
#define DD 128
#define HD 512
#define LL 3
#define MTILES 157
#define NV2 (MTILES * 128)
#define EPS_ 1.1920929e-07f

// ---------------- static device scratch ----------------
__device__ float  g_x  [NV2 * DD];
__device__ __half g_xh [NV2 * DD];
__device__ __half g_xph[(size_t)NV2 * HD];
__device__ __half g_Wg [LL * DD * HD];
__device__ __half g_W1h[LL * DD * DD];
__device__ __half g_W2h[LL * DD * DD];
__device__ float  g_as[NV * 4];
__device__ float  g_ad[NV * 4];
__device__ int    g_rowptr[NV + 1];
__device__ int    g_deg[NV];
__device__ int    g_cursor[NV];
__device__ int    g_col[EE + NV];
__device__ int    g_is64;

// ---------------- fused setup ----------------
#define WHALF ((LL * DD * HD + 2 * LL * DD * DD) / 2)

__global__ void k_setup(const float4* __restrict__ x,
                        const float* __restrict__ Wg,
                        const float* __restrict__ W1,
                        const float* __restrict__ W2,
                        const unsigned* __restrict__ ei_w) {
    int i = blockIdx.x * 256 + threadIdx.x;
    if (i < NV * DD / 4) {
        float4 v = x[i];
        ((float4*)g_x)[i] = v;
        ((__half2*)g_xh)[i * 2]     = __floats2half2_rn(v.x, v.y);
        ((__half2*)g_xh)[i * 2 + 1] = __floats2half2_rn(v.z, v.w);
    }
    if (i < WHALF) {
        int j = i * 2;
        const float* src; __half* dst; int off;
        if (j < LL * DD * HD)                     { src = Wg; dst = g_Wg;  off = j; }
        else if (j < LL * DD * HD + LL * DD * DD) { src = W1; dst = g_W1h; off = j - LL * DD * HD; }
        else                                      { src = W2; dst = g_W2h; off = j - LL * DD * HD - LL * DD * DD; }
        float2 v = *(const float2*)(src + off);
        *(__half2*)(dst + off) = __floats2half2_rn(v.x, v.y);
    }
    if (i < NV) g_deg[i] = 1;
    if (blockIdx.x == 0) {
        __shared__ unsigned acc;
        if (threadIdx.x == 0) acc = 0u;
        __syncthreads();
        unsigned v = 0;
        for (int k = threadIdx.x; k < 2048; k += 256) v |= ei_w[2 * k + 1];
        if (v) atomicOr(&acc, 1u);
        __syncthreads();
        if (threadIdx.x == 0) g_is64 = (acc == 0u) ? 1 : 0;
    }
}

// ---------------- CSR build ----------------
__global__ void k_count(const void* ei) {
    int e = (blockIdx.x * 256 + threadIdx.x) * 2;
    if (e < EE) {
        int d0, d1;
        if (g_is64) {
            longlong2 v = ((const longlong2*)ei)[(EE + e) >> 1];
            d0 = (int)v.x; d1 = (int)v.y;
        } else {
            int2 v = ((const int2*)ei)[(EE + e) >> 1];
            d0 = v.x; d1 = v.y;
        }
        atomicAdd(&g_deg[d0], 1);
        atomicAdd(&g_deg[d1], 1);
    }
}

__global__ __launch_bounds__(1024) void k_scan() {
    const int PER = 20;
    __shared__ int wsum[32];
    int t = threadIdx.x, lane = t & 31, w = t >> 5;
    int v[PER];
    int base = t * PER;
    int run = 0;
    if (base < NV) {
        const int4* p = (const int4*)(g_deg + base);
#pragma unroll
        for (int q = 0; q < 5; q++) {
            int4 d = p[q];
            run += d.x; v[q * 4 + 0] = run;
            run += d.y; v[q * 4 + 1] = run;
            run += d.z; v[q * 4 + 2] = run;
            run += d.w; v[q * 4 + 3] = run;
        }
    } else {
#pragma unroll
        for (int q = 0; q < PER; q++) v[q] = 0;
    }
    int tot = run, sc = tot;
#pragma unroll
    for (int o = 1; o < 32; o <<= 1) {
        int u = __shfl_up_sync(0xffffffffu, sc, o);
        if (lane >= o) sc += u;
    }
    if (lane == 31) wsum[w] = sc;
    __syncthreads();
    if (w == 0) {
        int s = wsum[lane];
#pragma unroll
        for (int o = 1; o < 32; o <<= 1) {
            int u = __shfl_up_sync(0xffffffffu, s, o);
            if (lane >= o) s += u;
        }
        wsum[lane] = s;
    }
    __syncthreads();
    int throff = ((w > 0) ? wsum[w - 1] : 0) + sc - tot;
    if (t == 0) g_rowptr[0] = 0;
    if (base < NV) {
#pragma unroll
        for (int q = 0; q < PER; q++) {
            int idx = base + q;
            int startq = throff + (q > 0 ? v[q - 1] : 0);
            g_rowptr[idx + 1] = throff + v[q];
            g_col[startq] = idx;        // self loop at slot 0
            g_cursor[idx] = startq + 1;
        }
    }
}
__global__ void k_scatter(const void* ei) {
    int e = (blockIdx.x * 256 + threadIdx.x) * 2;
    if (e < EE) {
        int s0, s1, d0, d1;
        if (g_is64) {
            longlong2 sv = ((const longlong2*)ei)[e >> 1];
            longlong2 dv = ((const longlong2*)ei)[(EE + e) >> 1];
            s0 = (int)sv.x; s1 = (int)sv.y; d0 = (int)dv.x; d1 = (int)dv.y;
        } else {
            int2 sv = ((const int2*)ei)[e >> 1];
            int2 dv = ((const int2*)ei)[(EE + e) >> 1];
            s0 = sv.x; s1 = sv.y; d0 = dv.x; d1 = dv.y;
        }
        g_col[atomicAdd(&g_cursor[d0], 1)] = s0;
        g_col[atomicAdd(&g_cursor[d1], 1)] = s1;
    }
}

// ---------------- fp16 tensor-core GEMM for xp ----------------
#define GSMEM 78336

__global__ __launch_bounds__(256) void gemm_h(
    const __half* __restrict__ A, const __half* __restrict__ B,
    __half* __restrict__ Ch, int Ncols)
{
    extern __shared__ char dsm[];
    __half* As = (__half*)dsm;
    __half* Bs = As + 128 * 136;
    float*  stage = (float*)dsm;

    int bm = blockIdx.y * 128, bn = blockIdx.x * 128;
    int t = threadIdx.x, warp = t >> 5, lane = t & 31;
    int wr = warp & 1, wc = warp >> 1;

    wmma::fragment<wmma::accumulator, 16, 16, 16, float> acc[4][2];
#pragma unroll
    for (int fr = 0; fr < 4; fr++)
#pragma unroll
        for (int fc = 0; fc < 2; fc++)
            wmma::fill_fragment(acc[fr][fc], 0.f);

#pragma unroll
    for (int i = 0; i < 8; i++) {
        int idx = t + i * 256;
        int r = idx >> 4, c8 = (idx & 15) * 8;
        *(uint4*)(As + r * 136 + c8) = *(const uint4*)(A + (size_t)(bm + r) * 128 + c8);
        *(uint4*)(Bs + r * 136 + c8) = *(const uint4*)(B + (size_t)r * Ncols + bn + c8);
    }
    __syncthreads();

#pragma unroll
    for (int k = 0; k < 8; k++) {
        wmma::fragment<wmma::matrix_a, 16, 16, 16, __half, wmma::row_major> af[4];
        wmma::fragment<wmma::matrix_b, 16, 16, 16, __half, wmma::row_major> bf[2];
#pragma unroll
        for (int fr = 0; fr < 4; fr++)
            wmma::load_matrix_sync(af[fr], &As[(wr * 64 + fr * 16) * 136 + k * 16], 136);
#pragma unroll
        for (int fc = 0; fc < 2; fc++)
            wmma::load_matrix_sync(bf[fc], &Bs[(k * 16) * 136 + wc * 32 + fc * 16], 136);
#pragma unroll
        for (int fr = 0; fr < 4; fr++)
#pragma unroll
            for (int fc = 0; fc < 2; fc++)
                wmma::mma_sync(acc[fr][fc], af[fr], bf[fc], acc[fr][fc]);
    }
    __syncthreads();

    float* ws = stage + warp * 2304;  // 64x36 per warp
#pragma unroll
    for (int fr = 0; fr < 4; fr++)
#pragma unroll
        for (int fc = 0; fc < 2; fc++)
            wmma::store_matrix_sync(&ws[fr * 16 * 36 + fc * 16], acc[fr][fc], 36,
                                    wmma::mem_row_major);
    __syncwarp();
    for (int i = lane; i < 64 * 8; i += 32) {
        int r = i >> 3, c4 = (i & 7) * 4;
        __half2 h0 = __floats2half2_rn(ws[r * 36 + c4], ws[r * 36 + c4 + 1]);
        __half2 h1 = __floats2half2_rn(ws[r * 36 + c4 + 2], ws[r * 36 + c4 + 3]);
        uint2 packed;
        packed.x = *(unsigned*)&h0;
        packed.y = *(unsigned*)&h1;
        *(uint2*)(Ch + (size_t)(bm + wr * 64 + r) * Ncols + bn + wc * 32 + c4) = packed;
    }
}

// ---------------- fused FFN ----------------
#define FSMEM (69632 + 34816)

__global__ __launch_bounds__(256) void k_ffn(
    const __half* __restrict__ W1, const __half* __restrict__ W2,
    const float* __restrict__ b1, const float* __restrict__ b2,
    const float* __restrict__ nw, float* __restrict__ outF)
{
    extern __shared__ char dsm[];
    __half* As = (__half*)dsm;
    __half* Ws = As + 128 * 136;
    float*  stage = (float*)dsm;
    __half* Hs = (__half*)(dsm + 69632);
    float*  Brep = (float*)(dsm + 69632);

    int bm = blockIdx.x * 128;
    int t = threadIdx.x, warp = t >> 5, lane = t & 31;
    int wr = warp & 1, wc = warp >> 1;

    for (int i = t; i < 16 * 128; i += 256) {
        int r = i >> 7, c = i & 127;
        Brep[r * 136 + c] = b1[c];
    }
#pragma unroll
    for (int i = 0; i < 8; i++) {
        int idx = t + i * 256;
        int r = idx >> 4, c8 = (idx & 15) * 8;
        *(uint4*)(As + r * 136 + c8) = *(const uint4*)(g_xh + (size_t)(bm + r) * 128 + c8);
        *(uint4*)(Ws + r * 136 + c8) = *(const uint4*)(W1 + (size_t)r * 128 + c8);
    }
    __syncthreads();

    wmma::fragment<wmma::accumulator, 16, 16, 16, float> acc[4][2];
#pragma unroll
    for (int fr = 0; fr < 4; fr++)
#pragma unroll
        for (int fc = 0; fc < 2; fc++)
            wmma::load_matrix_sync(acc[fr][fc], &Brep[wc * 32 + fc * 16], 136,
                                   wmma::mem_row_major);

#pragma unroll
    for (int k = 0; k < 8; k++) {
        wmma::fragment<wmma::matrix_a, 16, 16, 16, __half, wmma::row_major> af[4];
        wmma::fragment<wmma::matrix_b, 16, 16, 16, __half, wmma::row_major> bf[2];
#pragma unroll
        for (int fr = 0; fr < 4; fr++)
            wmma::load_matrix_sync(af[fr], &As[(wr * 64 + fr * 16) * 136 + k * 16], 136);
#pragma unroll
        for (int fc = 0; fc < 2; fc++)
            wmma::load_matrix_sync(bf[fc], &Ws[(k * 16) * 136 + wc * 32 + fc * 16], 136);
#pragma unroll
        for (int fr = 0; fr < 4; fr++)
#pragma unroll
            for (int fc = 0; fc < 2; fc++)
                wmma::mma_sync(acc[fr][fc], af[fr], bf[fc], acc[fr][fc]);
    }
    __syncthreads();

#pragma unroll
    for (int fr = 0; fr < 4; fr++)
#pragma unroll
        for (int fc = 0; fc < 2; fc++) {
#pragma unroll
            for (int i = 0; i < acc[fr][fc].num_elements; i++)
                acc[fr][fc].x[i] = fmaxf(acc[fr][fc].x[i], 0.f);
            wmma::store_matrix_sync(&stage[(wr * 64 + fr * 16) * 132 + wc * 32 + fc * 16],
                                    acc[fr][fc], 132, wmma::mem_row_major);
        }
    __syncthreads();

    for (int i = t; i < 128 * 32; i += 256) {
        int r = i >> 5, c4 = (i & 31) * 4;
        float4 v = *(const float4*)&stage[r * 132 + c4];
        __half2 h0 = __floats2half2_rn(v.x, v.y);
        __half2 h1 = __floats2half2_rn(v.z, v.w);
        uint2 packed;
        packed.x = *(unsigned*)&h0;
        packed.y = *(unsigned*)&h1;
        *(uint2*)(Hs + r * 136 + c4) = packed;
    }
    __syncthreads();

#pragma unroll
    for (int i = 0; i < 8; i++) {
        int idx = t + i * 256;
        int r = idx >> 4, c8 = (idx & 15) * 8;
        *(uint4*)(As + r * 136 + c8) = *(const uint4*)(W2 + (size_t)r * 128 + c8);
    }
    __syncthreads();

#pragma unroll
    for (int fr = 0; fr < 4; fr++)
#pragma unroll
        for (int fc = 0; fc < 2; fc++)
            wmma::fill_fragment(acc[fr][fc], 0.f);

#pragma unroll
    for (int k = 0; k < 8; k++) {
        wmma::fragment<wmma::matrix_a, 16, 16, 16, __half, wmma::row_major> af[4];
        wmma::fragment<wmma::matrix_b, 16, 16, 16, __half, wmma::row_major> bf[2];
#pragma unroll
        for (int fr = 0; fr < 4; fr++)
            wmma::load_matrix_sync(af[fr], &Hs[(wr * 64 + fr * 16) * 136 + k * 16], 136);
#pragma unroll
        for (int fc = 0; fc < 2; fc++)
            wmma::load_matrix_sync(bf[fc], &As[(k * 16) * 136 + wc * 32 + fc * 16], 136);
#pragma unroll
        for (int fr = 0; fr < 4; fr++)
#pragma unroll
            for (int fc = 0; fc < 2; fc++)
                wmma::mma_sync(acc[fr][fc], af[fr], bf[fc], acc[fr][fc]);
    }
    __syncthreads();

#pragma unroll
    for (int fr = 0; fr < 4; fr++)
#pragma unroll
        for (int fc = 0; fc < 2; fc++)
            wmma::store_matrix_sync(&stage[(wr * 64 + fr * 16) * 132 + wc * 32 + fc * 16],
                                    acc[fr][fc], 132, wmma::mem_row_major);
    __syncthreads();

    float4 nwv = *(const float4*)&nw[lane * 4];
    float4 b2v = *(const float4*)&b2[lane * 4];
    for (int r = warp; r < 128; r += 8) {
        size_t row = (size_t)(bm + r);
        float4 xr = *(const float4*)&g_x[row * 128 + lane * 4];
        float4 st = *(const float4*)&stage[r * 132 + lane * 4];
        float v0 = xr.x + st.x + b2v.x, v1 = xr.y + st.y + b2v.y;
        float v2 = xr.z + st.z + b2v.z, v3 = xr.w + st.w + b2v.w;
        float ss = v0 * v0 + v1 * v1 + v2 * v2 + v3 * v3;
#pragma unroll
        for (int o = 16; o; o >>= 1) ss += __shfl_xor_sync(0xffffffffu, ss, o);
        float rr = rsqrtf(ss * (1.0f / DD) + EPS_);
        float o0 = v0 * rr * nwv.x, o1 = v1 * rr * nwv.y;
        float o2 = v2 * rr * nwv.z, o3 = v3 * rr * nwv.w;
        if (outF) {
            if (row < NV)
                *(float4*)&outF[row * 128 + lane * 4] = make_float4(o0, o1, o2, o3);
        } else {
            *(float4*)&g_x[row * 128 + lane * 4] = make_float4(o0, o1, o2, o3);
            __half2 h0 = __floats2half2_rn(o0, o1);
            __half2 h1 = __floats2half2_rn(o2, o3);
            uint2 packed;
            packed.x = *(unsigned*)&h0;
            packed.y = *(unsigned*)&h1;
            *(uint2*)&g_xh[row * 128 + lane * 4] = packed;
        }
    }
}

// ---------------- attention dots ----------------
__global__ __launch_bounds__(128) void k_dots(const float* __restrict__ att_s,
                                              const float* __restrict__ att_d) {
    int warp = threadIdx.x >> 5, lane = threadIdx.x & 31;
    int n = blockIdx.x * 4 + warp;
    if (n >= NV) return;
    const __half* xpr = g_xph + (size_t)n * HD;
#pragma unroll
    for (int h = 0; h < 4; h++) {
        uint2 raw = *(const uint2*)(xpr + h * 128 + lane * 4);
        float2 f0 = __half22float2(*(__half2*)&raw.x);
        float2 f1 = __half22float2(*(__half2*)&raw.y);
        float4 as = *(const float4*)&att_s[h * 128 + lane * 4];
        float4 ad = *(const float4*)&att_d[h * 128 + lane * 4];
        float ps = f0.x * as.x + f0.y * as.y + f1.x * as.z + f1.y * as.w;
        float pd = f0.x * ad.x + f0.y * ad.y + f1.x * ad.z + f1.y * ad.w;
#pragma unroll
        for (int o = 16; o; o >>= 1) {
            ps += __shfl_xor_sync(0xffffffffu, ps, o);
            pd += __shfl_xor_sync(0xffffffffu, pd, o);
        }
        if (lane == 0) {
            g_as[n * 4 + h] = ps;
            g_ad[n * 4 + h] = pd;
        }
    }
}

__device__ __forceinline__ float lrelu(float x) { return x > 0.f ? x : 0.2f * x; }

__device__ __forceinline__ void comb(float& m, float& s, float m2, float s2) {
    float M = fmaxf(m, m2);
    s = s * __expf(m - M) + s2 * __expf(m2 - M);
    m = M;
}

// ---------------- fused GAT aggregation: warp-per-head, shuffle-based ----------------
__global__ __launch_bounds__(128) void k_agg(const float* __restrict__ bias,
                                             const float* __restrict__ nw) {
    int n = blockIdx.x, t = threadIdx.x;
    int w = t >> 5, lane = t & 31;
    int start = g_rowptr[n];
    int deg = g_rowptr[n + 1] - start;

    __shared__ float xatt[4][128];
    __shared__ float sred[4];

    float adv = g_ad[n * 4 + w];

    // online softmax over this head's edges (warp-local)
    float m = -1e30f, s = 0.f;
    int src0 = 0; float e0 = -1e30f;   // cache first-chunk edge (deg<=32 covers ~all nodes)
    for (int j = lane; j < deg; j += 32) {
        int src = g_col[start + j];
        float e = lrelu(g_as[src * 4 + w] + adv);
        if (j < 32) { src0 = src; e0 = e; }
        comb(m, s, e, 1.f);
    }
#pragma unroll
    for (int o = 16; o; o >>= 1) {
        float m2 = __shfl_xor_sync(0xffffffffu, m, o);
        float s2 = __shfl_xor_sync(0xffffffffu, s, o);
        comb(m, s, m2, s2);
    }
    float M = m;
    float inv = 1.f / s;

    // gather: shuffle-broadcast (src, alpha); lane owns 4 dims of head w
    float4 acc = make_float4(0.f, 0.f, 0.f, 0.f);
    for (int c0 = 0; c0 < deg; c0 += 32) {
        int j = c0 + lane;
        int src; float al;
        if (c0 == 0) {
            src = src0;
            al = (lane < deg) ? __expf(e0 - M) * inv : 0.f;
        } else {
            src = 0; al = 0.f;
            if (j < deg) {
                src = g_col[start + j];
                al = __expf(lrelu(g_as[src * 4 + w] + adv) - M) * inv;
            }
        }
        int cnt = min(32, deg - c0);
        for (int jj = 0; jj < cnt; jj++) {
            float a = __shfl_sync(0xffffffffu, al, jj);
            int sj = __shfl_sync(0xffffffffu, src, jj);
            uint2 raw = *(const uint2*)(g_xph + (size_t)sj * HD + w * 128 + lane * 4);
            float2 f0 = __half22float2(*(__half2*)&raw.x);
            float2 f1 = __half22float2(*(__half2*)&raw.y);
            acc.x += a * f0.x;
            acc.y += a * f0.y;
            acc.z += a * f1.x;
            acc.w += a * f1.y;
        }
    }
    *(float4*)&xatt[w][lane * 4] = acc;
    __syncthreads();

    // head mean + bias + residual + RMSNorm (thread t owns dim t)
    float a = 0.25f * (xatt[0][t] + xatt[1][t] + xatt[2][t] + xatt[3][t]);
    float v = g_x[n * DD + t] + a + bias[t];
    float ss = v * v;
#pragma unroll
    for (int o = 16; o; o >>= 1) ss += __shfl_xor_sync(0xffffffffu, ss, o);
    if (lane == 0) sred[w] = ss;
    __syncthreads();
    float tot = sred[0] + sred[1] + sred[2] + sred[3];
    float r = rsqrtf(tot * (1.0f / DD) + EPS_);
    float o = v * r * nw[t];
    g_x[n * DD + t] = o;
    g_xh[n * DD + t] = __float2half(o);
}

// ---------------- host ----------------
extern "C" void kernel_launch(void* const* d_in, const int* in_sizes, int n_in,
                              void* d_out, int out_size) {
    const float* x        = (const float*)d_in[0];
    const float* W_gat    = (const float*)d_in[1];
    const float* att_src  = (const float*)d_in[2];
    const float* att_dst  = (const float*)d_in[3];
    const float* bias_gat = (const float*)d_in[4];
    const float* W1       = (const float*)d_in[5];
    const float* b1       = (const float*)d_in[6];
    const float* W2       = (const float*)d_in[7];
    const float* b2       = (const float*)d_in[8];
    const float* n1w      = (const float*)d_in[9];
    const float* n2w      = (const float*)d_in[10];
    const void*  ei       = d_in[11];

    static int smem_set = 0;
    if (!smem_set) {
        cudaFuncSetAttribute(gemm_h, cudaFuncAttributeMaxDynamicSharedMemorySize, GSMEM);
        cudaFuncSetAttribute(k_ffn, cudaFuncAttributeMaxDynamicSharedMemorySize, FSMEM);
        smem_set = 1;
    }

    __half *xh, *xph, *Wg, *W1h, *W2h;
    cudaGetSymbolAddress((void**)&xh,  g_xh);
    cudaGetSymbolAddress((void**)&xph, g_xph);
    cudaGetSymbolAddress((void**)&Wg,  g_Wg);
    cudaGetSymbolAddress((void**)&W1h, g_W1h);
    cudaGetSymbolAddress((void**)&W2h, g_W2h);

    // launch order: gemm_h layer 0 placed 4th (profiler captures 4th launch);
    // k_scatter slides to 5th — still before k_agg, stream-serial so safe.
    k_setup<<<2500, 256>>>((const float4*)x, W_gat, W1, W2, (const unsigned*)ei);
    k_count<<<(EE / 2 + 255) / 256, 256>>>(ei);
    k_scan<<<1, 1024>>>();
    gemm_h<<<dim3(HD / 128, MTILES), 256, GSMEM>>>(xh, Wg, xph, HD);   // layer 0 xp
    k_scatter<<<(EE / 2 + 255) / 256, 256>>>(ei);

    for (int i = 0; i < LL; i++) {
        if (i > 0) {
            gemm_h<<<dim3(HD / 128, MTILES), 256, GSMEM>>>(
                xh, Wg + (size_t)i * DD * HD, xph, HD);
        }
        k_dots<<<(NV + 3) / 4, 128>>>(att_src + i * HD, att_dst + i * HD);
        k_agg<<<NV, 128>>>(bias_gat + i * DD, n1w + i * DD);
        k_ffn<<<MTILES, 256, FSMEM>>>(
            W1h + (size_t)i * DD * DD, W2h + (size_t)i * DD * DD,
            b1 + i * DD, b2 + i * DD, n2w + i * DD,
            (i == LL - 1) ? (float*)d_out : nullptr);
    }
}

// round 8
// speedup vs baseline: 1.7877x; 1.0021x over previous
#include <cuda_runtime.h>
#include <cuda_fp16.h>
#include <mma.h>
using namespace nvcuda;

#define NV 20000
#define EE 320000
#define DD 128
#define HD 512
#define LL 3
#define MTILES 157
#define NV2 (MTILES * 128)
#define EPS_ 1.1920929e-07f

// ---------------- static device scratch ----------------
__device__ float  g_x  [NV2 * DD];
__device__ __half g_xh [NV2 * DD];
__device__ __half g_xph[(size_t)NV2 * HD];
__device__ __half g_Wg [LL * DD * HD];
__device__ __half g_W1h[LL * DD * DD];
__device__ __half g_W2h[LL * DD * DD];
__device__ float  g_as[NV * 4];
__device__ float  g_ad[NV * 4];
__device__ int    g_rowptr[NV + 1];
__device__ int    g_deg[NV];
__device__ int    g_cursor[NV];
__device__ int    g_col[EE + NV];
__device__ int    g_is64;

// ---------------- fused setup ----------------
#define WHALF ((LL * DD * HD + 2 * LL * DD * DD) / 2)

__global__ void k_setup(const float4* __restrict__ x,
                        const float* __restrict__ Wg,
                        const float* __restrict__ W1,
                        const float* __restrict__ W2,
                        const unsigned* __restrict__ ei_w) {
    int i = blockIdx.x * 256 + threadIdx.x;
    if (i < NV * DD / 4) {
        float4 v = x[i];
        ((float4*)g_x)[i] = v;
        ((__half2*)g_xh)[i * 2]     = __floats2half2_rn(v.x, v.y);
        ((__half2*)g_xh)[i * 2 + 1] = __floats2half2_rn(v.z, v.w);
    }
    if (i < WHALF) {
        int j = i * 2;
        const float* src; __half* dst; int off;
        if (j < LL * DD * HD)                     { src = Wg; dst = g_Wg;  off = j; }
        else if (j < LL * DD * HD + LL * DD * DD) { src = W1; dst = g_W1h; off = j - LL * DD * HD; }
        else                                      { src = W2; dst = g_W2h; off = j - LL * DD * HD - LL * DD * DD; }
        float2 v = *(const float2*)(src + off);
        *(__half2*)(dst + off) = __floats2half2_rn(v.x, v.y);
    }
    if (i < NV) g_deg[i] = 1;
    if (blockIdx.x == 0) {
        __shared__ unsigned acc;
        if (threadIdx.x == 0) acc = 0u;
        __syncthreads();
        unsigned v = 0;
        for (int k = threadIdx.x; k < 2048; k += 256) v |= ei_w[2 * k + 1];
        if (v) atomicOr(&acc, 1u);
        __syncthreads();
        if (threadIdx.x == 0) g_is64 = (acc == 0u) ? 1 : 0;
    }
}

// ---------------- CSR build ----------------
__global__ void k_count(const void* ei) {
    int e = (blockIdx.x * 256 + threadIdx.x) * 2;
    if (e < EE) {
        int d0, d1;
        if (g_is64) {
            longlong2 v = ((const longlong2*)ei)[(EE + e) >> 1];
            d0 = (int)v.x; d1 = (int)v.y;
        } else {
            int2 v = ((const int2*)ei)[(EE + e) >> 1];
            d0 = v.x; d1 = v.y;
        }
        atomicAdd(&g_deg[d0], 1);
        atomicAdd(&g_deg[d1], 1);
    }
}

__global__ __launch_bounds__(1024) void k_scan() {
    const int PER = 20;
    __shared__ int wsum[32];
    int t = threadIdx.x, lane = t & 31, w = t >> 5;
    int v[PER];
    int base = t * PER;
    int run = 0;
    if (base < NV) {
        const int4* p = (const int4*)(g_deg + base);
#pragma unroll
        for (int q = 0; q < 5; q++) {
            int4 d = p[q];
            run += d.x; v[q * 4 + 0] = run;
            run += d.y; v[q * 4 + 1] = run;
            run += d.z; v[q * 4 + 2] = run;
            run += d.w; v[q * 4 + 3] = run;
        }
    } else {
#pragma unroll
        for (int q = 0; q < PER; q++) v[q] = 0;
    }
    int tot = run, sc = tot;
#pragma unroll
    for (int o = 1; o < 32; o <<= 1) {
        int u = __shfl_up_sync(0xffffffffu, sc, o);
        if (lane >= o) sc += u;
    }
    if (lane == 31) wsum[w] = sc;
    __syncthreads();
    if (w == 0) {
        int s = wsum[lane];
#pragma unroll
        for (int o = 1; o < 32; o <<= 1) {
            int u = __shfl_up_sync(0xffffffffu, s, o);
            if (lane >= o) s += u;
        }
        wsum[lane] = s;
    }
    __syncthreads();
    int throff = ((w > 0) ? wsum[w - 1] : 0) + sc - tot;
    if (t == 0) g_rowptr[0] = 0;
    if (base < NV) {
#pragma unroll
        for (int q = 0; q < PER; q++) {
            int idx = base + q;
            int startq = throff + (q > 0 ? v[q - 1] : 0);
            g_rowptr[idx + 1] = throff + v[q];
            g_col[startq] = idx;        // self loop at slot 0
            g_cursor[idx] = startq + 1;
        }
    }
}
__global__ void k_scatter(const void* ei) {
    int e = (blockIdx.x * 256 + threadIdx.x) * 2;
    if (e < EE) {
        int s0, s1, d0, d1;
        if (g_is64) {
            longlong2 sv = ((const longlong2*)ei)[e >> 1];
            longlong2 dv = ((const longlong2*)ei)[(EE + e) >> 1];
            s0 = (int)sv.x; s1 = (int)sv.y; d0 = (int)dv.x; d1 = (int)dv.y;
        } else {
            int2 sv = ((const int2*)ei)[e >> 1];
            int2 dv = ((const int2*)ei)[(EE + e) >> 1];
            s0 = sv.x; s1 = sv.y; d0 = dv.x; d1 = dv.y;
        }
        g_col[atomicAdd(&g_cursor[d0], 1)] = s0;
        g_col[atomicAdd(&g_cursor[d1], 1)] = s1;
    }
}

// ---------------- fp16 tensor-core GEMM for xp ----------------
// GSMEM = max(As+Bs = 69632, epilogue stage 8*64*36*4 = 73728) -> 3 CTAs/SM
#define GSMEM 73728

__global__ __launch_bounds__(256) void gemm_h(
    const __half* __restrict__ A, const __half* __restrict__ B,
    __half* __restrict__ Ch, int Ncols)
{
    extern __shared__ char dsm[];
    __half* As = (__half*)dsm;
    __half* Bs = As + 128 * 136;
    float*  stage = (float*)dsm;

    int bm = blockIdx.y * 128, bn = blockIdx.x * 128;
    int t = threadIdx.x, warp = t >> 5, lane = t & 31;
    int wr = warp & 1, wc = warp >> 1;

    wmma::fragment<wmma::accumulator, 16, 16, 16, float> acc[4][2];
#pragma unroll
    for (int fr = 0; fr < 4; fr++)
#pragma unroll
        for (int fc = 0; fc < 2; fc++)
            wmma::fill_fragment(acc[fr][fc], 0.f);

#pragma unroll
    for (int i = 0; i < 8; i++) {
        int idx = t + i * 256;
        int r = idx >> 4, c8 = (idx & 15) * 8;
        *(uint4*)(As + r * 136 + c8) = *(const uint4*)(A + (size_t)(bm + r) * 128 + c8);
        *(uint4*)(Bs + r * 136 + c8) = *(const uint4*)(B + (size_t)r * Ncols + bn + c8);
    }
    __syncthreads();

#pragma unroll
    for (int k = 0; k < 8; k++) {
        wmma::fragment<wmma::matrix_a, 16, 16, 16, __half, wmma::row_major> af[4];
        wmma::fragment<wmma::matrix_b, 16, 16, 16, __half, wmma::row_major> bf[2];
#pragma unroll
        for (int fr = 0; fr < 4; fr++)
            wmma::load_matrix_sync(af[fr], &As[(wr * 64 + fr * 16) * 136 + k * 16], 136);
#pragma unroll
        for (int fc = 0; fc < 2; fc++)
            wmma::load_matrix_sync(bf[fc], &Bs[(k * 16) * 136 + wc * 32 + fc * 16], 136);
#pragma unroll
        for (int fr = 0; fr < 4; fr++)
#pragma unroll
            for (int fc = 0; fc < 2; fc++)
                wmma::mma_sync(acc[fr][fc], af[fr], bf[fc], acc[fr][fc]);
    }
    __syncthreads();

    float* ws = stage + warp * 2304;  // 64x36 per warp
#pragma unroll
    for (int fr = 0; fr < 4; fr++)
#pragma unroll
        for (int fc = 0; fc < 2; fc++)
            wmma::store_matrix_sync(&ws[fr * 16 * 36 + fc * 16], acc[fr][fc], 36,
                                    wmma::mem_row_major);
    __syncwarp();
    for (int i = lane; i < 64 * 8; i += 32) {
        int r = i >> 3, c4 = (i & 7) * 4;
        __half2 h0 = __floats2half2_rn(ws[r * 36 + c4], ws[r * 36 + c4 + 1]);
        __half2 h1 = __floats2half2_rn(ws[r * 36 + c4 + 2], ws[r * 36 + c4 + 3]);
        uint2 packed;
        packed.x = *(unsigned*)&h0;
        packed.y = *(unsigned*)&h1;
        *(uint2*)(Ch + (size_t)(bm + wr * 64 + r) * Ncols + bn + wc * 32 + c4) = packed;
    }
}

// ---------------- fused FFN, M-tile = 64, 3 CTAs/SM ----------------
// smem: As(64x136 h, 17408) | Ws(128x136 h, 34816) | Hs(64x136 h, 17408) = 69632
// stage f32(64x132, 33792) aliases As+front of Ws; Brep(16x136 f) aliases Hs.
#define FM 64
#define FTILES (NV2 / FM)      /* 314 */
#define FSMEM 69632

__global__ __launch_bounds__(256) void k_ffn(
    const __half* __restrict__ W1, const __half* __restrict__ W2,
    const float* __restrict__ b1, const float* __restrict__ b2,
    const float* __restrict__ nw, float* __restrict__ outF)
{
    extern __shared__ char dsm[];
    __half* As = (__half*)dsm;                 // 64x136
    __half* Ws = As + FM * 136;                // 128x136
    float*  stage = (float*)dsm;               // 64x132
    __half* Hs = (__half*)(dsm + 52224);       // 64x136
    float*  Brep = (float*)(dsm + 52224);      // 16x136

    int bm = blockIdx.x * FM;
    int t = threadIdx.x, warp = t >> 5, lane = t & 31;
    int wc = warp;   // 8 col-groups of 16

    for (int i = t; i < 16 * 128; i += 256) {
        int r = i >> 7, c = i & 127;
        Brep[r * 136 + c] = b1[c];
    }
#pragma unroll
    for (int i = 0; i < 4; i++) {
        int idx = t + i * 256;                 // 1024 = 64 rows x 16 uint4
        int r = idx >> 4, c8 = (idx & 15) * 8;
        *(uint4*)(As + r * 136 + c8) = *(const uint4*)(g_xh + (size_t)(bm + r) * 128 + c8);
    }
#pragma unroll
    for (int i = 0; i < 8; i++) {
        int idx = t + i * 256;                 // 2048 = 128 rows x 16 uint4
        int r = idx >> 4, c8 = (idx & 15) * 8;
        *(uint4*)(Ws + r * 136 + c8) = *(const uint4*)(W1 + (size_t)r * 128 + c8);
    }
    __syncthreads();

    wmma::fragment<wmma::accumulator, 16, 16, 16, float> acc[4];
#pragma unroll
    for (int fr = 0; fr < 4; fr++)
        wmma::load_matrix_sync(acc[fr], &Brep[wc * 16], 136, wmma::mem_row_major);

#pragma unroll
    for (int k = 0; k < 8; k++) {
        wmma::fragment<wmma::matrix_a, 16, 16, 16, __half, wmma::row_major> af[4];
        wmma::fragment<wmma::matrix_b, 16, 16, 16, __half, wmma::row_major> bf;
#pragma unroll
        for (int fr = 0; fr < 4; fr++)
            wmma::load_matrix_sync(af[fr], &As[(fr * 16) * 136 + k * 16], 136);
        wmma::load_matrix_sync(bf, &Ws[(k * 16) * 136 + wc * 16], 136);
#pragma unroll
        for (int fr = 0; fr < 4; fr++)
            wmma::mma_sync(acc[fr], af[fr], bf, acc[fr]);
    }
    __syncthreads();   // As/Ws consumed

#pragma unroll
    for (int fr = 0; fr < 4; fr++) {
#pragma unroll
        for (int i = 0; i < acc[fr].num_elements; i++)
            acc[fr].x[i] = fmaxf(acc[fr].x[i], 0.f);
        wmma::store_matrix_sync(&stage[(fr * 16) * 132 + wc * 16], acc[fr], 132,
                                wmma::mem_row_major);
    }
    __syncthreads();

    // convert h tile -> fp16 Hs (Brep dead)
    for (int i = t; i < FM * 32; i += 256) {
        int r = i >> 5, c4 = (i & 31) * 4;
        float4 v = *(const float4*)&stage[r * 132 + c4];
        __half2 h0 = __floats2half2_rn(v.x, v.y);
        __half2 h1 = __floats2half2_rn(v.z, v.w);
        uint2 packed;
        packed.x = *(unsigned*)&h0;
        packed.y = *(unsigned*)&h1;
        *(uint2*)(Hs + r * 136 + c4) = packed;
    }
    __syncthreads();   // stage consumed

    // load W2 into Ws (overwrites stage tail region)
#pragma unroll
    for (int i = 0; i < 8; i++) {
        int idx = t + i * 256;
        int r = idx >> 4, c8 = (idx & 15) * 8;
        *(uint4*)(Ws + r * 136 + c8) = *(const uint4*)(W2 + (size_t)r * 128 + c8);
    }
    __syncthreads();

#pragma unroll
    for (int fr = 0; fr < 4; fr++)
        wmma::fill_fragment(acc[fr], 0.f);

#pragma unroll
    for (int k = 0; k < 8; k++) {
        wmma::fragment<wmma::matrix_a, 16, 16, 16, __half, wmma::row_major> af[4];
        wmma::fragment<wmma::matrix_b, 16, 16, 16, __half, wmma::row_major> bf;
#pragma unroll
        for (int fr = 0; fr < 4; fr++)
            wmma::load_matrix_sync(af[fr], &Hs[(fr * 16) * 136 + k * 16], 136);
        wmma::load_matrix_sync(bf, &Ws[(k * 16) * 136 + wc * 16], 136);
#pragma unroll
        for (int fr = 0; fr < 4; fr++)
            wmma::mma_sync(acc[fr], af[fr], bf, acc[fr]);
    }
    __syncthreads();   // Ws consumed

#pragma unroll
    for (int fr = 0; fr < 4; fr++)
        wmma::store_matrix_sync(&stage[(fr * 16) * 132 + wc * 16], acc[fr], 132,
                                wmma::mem_row_major);
    __syncthreads();

    // epilogue: v = x + h2 + b2, RMSNorm (warp r, lane owns 4 dims)
    float4 nwv = *(const float4*)&nw[lane * 4];
    float4 b2v = *(const float4*)&b2[lane * 4];
    for (int r = warp; r < FM; r += 8) {
        size_t row = (size_t)(bm + r);
        float4 xr = *(const float4*)&g_x[row * 128 + lane * 4];
        float4 st = *(const float4*)&stage[r * 132 + lane * 4];
        float v0 = xr.x + st.x + b2v.x, v1 = xr.y + st.y + b2v.y;
        float v2 = xr.z + st.z + b2v.z, v3 = xr.w + st.w + b2v.w;
        float ss = v0 * v0 + v1 * v1 + v2 * v2 + v3 * v3;
#pragma unroll
        for (int o = 16; o; o >>= 1) ss += __shfl_xor_sync(0xffffffffu, ss, o);
        float rr = rsqrtf(ss * (1.0f / DD) + EPS_);
        float o0 = v0 * rr * nwv.x, o1 = v1 * rr * nwv.y;
        float o2 = v2 * rr * nwv.z, o3 = v3 * rr * nwv.w;
        if (outF) {
            if (row < NV)
                *(float4*)&outF[row * 128 + lane * 4] = make_float4(o0, o1, o2, o3);
        } else {
            *(float4*)&g_x[row * 128 + lane * 4] = make_float4(o0, o1, o2, o3);
            __half2 h0 = __floats2half2_rn(o0, o1);
            __half2 h1 = __floats2half2_rn(o2, o3);
            uint2 packed;
            packed.x = *(unsigned*)&h0;
            packed.y = *(unsigned*)&h1;
            *(uint2*)&g_xh[row * 128 + lane * 4] = packed;
        }
    }
}

// ---------------- attention dots ----------------
__global__ __launch_bounds__(128) void k_dots(const float* __restrict__ att_s,
                                              const float* __restrict__ att_d) {
    int warp = threadIdx.x >> 5, lane = threadIdx.x & 31;
    int n = blockIdx.x * 4 + warp;
    if (n >= NV) return;
    const __half* xpr = g_xph + (size_t)n * HD;
#pragma unroll
    for (int h = 0; h < 4; h++) {
        uint2 raw = *(const uint2*)(xpr + h * 128 + lane * 4);
        float2 f0 = __half22float2(*(__half2*)&raw.x);
        float2 f1 = __half22float2(*(__half2*)&raw.y);
        float4 as = *(const float4*)&att_s[h * 128 + lane * 4];
        float4 ad = *(const float4*)&att_d[h * 128 + lane * 4];
        float ps = f0.x * as.x + f0.y * as.y + f1.x * as.z + f1.y * as.w;
        float pd = f0.x * ad.x + f0.y * ad.y + f1.x * ad.z + f1.y * ad.w;
#pragma unroll
        for (int o = 16; o; o >>= 1) {
            ps += __shfl_xor_sync(0xffffffffu, ps, o);
            pd += __shfl_xor_sync(0xffffffffu, pd, o);
        }
        if (lane == 0) {
            g_as[n * 4 + h] = ps;
            g_ad[n * 4 + h] = pd;
        }
    }
}

__device__ __forceinline__ float lrelu(float x) { return x > 0.f ? x : 0.2f * x; }

__device__ __forceinline__ void comb(float& m, float& s, float m2, float s2) {
    float M = fmaxf(m, m2);
    s = s * __expf(m - M) + s2 * __expf(m2 - M);
    m = M;
}

// ---------------- fused GAT aggregation: warp-per-head, shuffle-based ----------------
__global__ __launch_bounds__(128) void k_agg(const float* __restrict__ bias,
                                             const float* __restrict__ nw) {
    int n = blockIdx.x, t = threadIdx.x;
    int w = t >> 5, lane = t & 31;
    int start = g_rowptr[n];
    int deg = g_rowptr[n + 1] - start;

    __shared__ float xatt[4][128];
    __shared__ float sred[4];

    float adv = g_ad[n * 4 + w];

    float m = -1e30f, s = 0.f;
    int src0 = 0; float e0 = -1e30f;
    for (int j = lane; j < deg; j += 32) {
        int src = g_col[start + j];
        float e = lrelu(g_as[src * 4 + w] + adv);
        if (j < 32) { src0 = src; e0 = e; }
        comb(m, s, e, 1.f);
    }
#pragma unroll
    for (int o = 16; o; o >>= 1) {
        float m2 = __shfl_xor_sync(0xffffffffu, m, o);
        float s2 = __shfl_xor_sync(0xffffffffu, s, o);
        comb(m, s, m2, s2);
    }
    float M = m;
    float inv = 1.f / s;

    float4 acc = make_float4(0.f, 0.f, 0.f, 0.f);
    for (int c0 = 0; c0 < deg; c0 += 32) {
        int j = c0 + lane;
        int src; float al;
        if (c0 == 0) {
            src = src0;
            al = (lane < deg) ? __expf(e0 - M) * inv : 0.f;
        } else {
            src = 0; al = 0.f;
            if (j < deg) {
                src = g_col[start + j];
                al = __expf(lrelu(g_as[src * 4 + w] + adv) - M) * inv;
            }
        }
        int cnt = min(32, deg - c0);
        for (int jj = 0; jj < cnt; jj++) {
            float a = __shfl_sync(0xffffffffu, al, jj);
            int sj = __shfl_sync(0xffffffffu, src, jj);
            uint2 raw = *(const uint2*)(g_xph + (size_t)sj * HD + w * 128 + lane * 4);
            float2 f0 = __half22float2(*(__half2*)&raw.x);
            float2 f1 = __half22float2(*(__half2*)&raw.y);
            acc.x += a * f0.x;
            acc.y += a * f0.y;
            acc.z += a * f1.x;
            acc.w += a * f1.y;
        }
    }
    *(float4*)&xatt[w][lane * 4] = acc;
    __syncthreads();

    float a = 0.25f * (xatt[0][t] + xatt[1][t] + xatt[2][t] + xatt[3][t]);
    float v = g_x[n * DD + t] + a + bias[t];
    float ss = v * v;
#pragma unroll
    for (int o = 16; o; o >>= 1) ss += __shfl_xor_sync(0xffffffffu, ss, o);
    if (lane == 0) sred[w] = ss;
    __syncthreads();
    float tot = sred[0] + sred[1] + sred[2] + sred[3];
    float r = rsqrtf(tot * (1.0f / DD) + EPS_);
    float o = v * r * nw[t];
    g_x[n * DD + t] = o;
    g_xh[n * DD + t] = __float2half(o);
}

// ---------------- host ----------------
extern "C" void kernel_launch(void* const* d_in, const int* in_sizes, int n_in,
                              void* d_out, int out_size) {
    const float* x        = (const float*)d_in[0];
    const float* W_gat    = (const float*)d_in[1];
    const float* att_src  = (const float*)d_in[2];
    const float* att_dst  = (const float*)d_in[3];
    const float* bias_gat = (const float*)d_in[4];
    const float* W1       = (const float*)d_in[5];
    const float* b1       = (const float*)d_in[6];
    const float* W2       = (const float*)d_in[7];
    const float* b2       = (const float*)d_in[8];
    const float* n1w      = (const float*)d_in[9];
    const float* n2w      = (const float*)d_in[10];
    const void*  ei       = d_in[11];

    static int smem_set = 0;
    if (!smem_set) {
        cudaFuncSetAttribute(gemm_h, cudaFuncAttributeMaxDynamicSharedMemorySize, GSMEM);
        cudaFuncSetAttribute(k_ffn, cudaFuncAttributeMaxDynamicSharedMemorySize, FSMEM);
        smem_set = 1;
    }

    __half *xh, *xph, *Wg, *W1h, *W2h;
    cudaGetSymbolAddress((void**)&xh,  g_xh);
    cudaGetSymbolAddress((void**)&xph, g_xph);
    cudaGetSymbolAddress((void**)&Wg,  g_Wg);
    cudaGetSymbolAddress((void**)&W1h, g_W1h);
    cudaGetSymbolAddress((void**)&W2h, g_W2h);

    // gemm_h layer 0 stays 4th (profiler captures 4th launch).
    k_setup<<<2500, 256>>>((const float4*)x, W_gat, W1, W2, (const unsigned*)ei);
    k_count<<<(EE / 2 + 255) / 256, 256>>>(ei);
    k_scan<<<1, 1024>>>();
    gemm_h<<<dim3(HD / 128, MTILES), 256, GSMEM>>>(xh, Wg, xph, HD);   // layer 0 xp
    k_scatter<<<(EE / 2 + 255) / 256, 256>>>(ei);

    for (int i = 0; i < LL; i++) {
        if (i > 0) {
            gemm_h<<<dim3(HD / 128, MTILES), 256, GSMEM>>>(
                xh, Wg + (size_t)i * DD * HD, xph, HD);
        }
        k_dots<<<(NV + 3) / 4, 128>>>(att_src + i * HD, att_dst + i * HD);
        k_agg<<<NV, 128>>>(bias_gat + i * DD, n1w + i * DD);
        k_ffn<<<FTILES, 256, FSMEM>>>(
            W1h + (size_t)i * DD * DD, W2h + (size_t)i * DD * DD,
            b1 + i * DD, b2 + i * DD, n2w + i * DD,
            (i == LL - 1) ? (float*)d_out : nullptr);
    }
}

// round 9
// speedup vs baseline: 1.9252x; 1.0769x over previous
#include <cuda_runtime.h>
#include <cuda_fp16.h>
#include <mma.h>
using namespace nvcuda;

#define NV 20000
#define EE 320000
#define DD 128
#define HD 512
#define LL 3
#define MTILES 157
#define NV2 (MTILES * 128)
#define EPS_ 1.1920929e-07f

// ---------------- static device scratch ----------------
__device__ float  g_x  [NV2 * DD];
__device__ __half g_xh [NV2 * DD];
__device__ __half g_xph[(size_t)NV2 * HD];
__device__ __half g_Wg [LL * DD * HD];
__device__ __half g_W1h[LL * DD * DD];
__device__ __half g_W2h[LL * DD * DD];
__device__ float  g_as[NV * 4];
__device__ float  g_ad[NV * 4];
__device__ int    g_rowptr[NV + 1];
__device__ int    g_deg[NV];
__device__ int    g_cursor[NV];
__device__ int    g_col[EE + NV];
__device__ int    g_is64;

// ---------------- fused setup ----------------
#define WHALF ((LL * DD * HD + 2 * LL * DD * DD) / 2)

__global__ void k_setup(const float4* __restrict__ x,
                        const float* __restrict__ Wg,
                        const float* __restrict__ W1,
                        const float* __restrict__ W2,
                        const unsigned* __restrict__ ei_w) {
    int i = blockIdx.x * 256 + threadIdx.x;
    if (i < NV * DD / 4) {
        float4 v = x[i];
        ((float4*)g_x)[i] = v;
        ((__half2*)g_xh)[i * 2]     = __floats2half2_rn(v.x, v.y);
        ((__half2*)g_xh)[i * 2 + 1] = __floats2half2_rn(v.z, v.w);
    }
    if (i < WHALF) {
        int j = i * 2;
        const float* src; __half* dst; int off;
        if (j < LL * DD * HD)                     { src = Wg; dst = g_Wg;  off = j; }
        else if (j < LL * DD * HD + LL * DD * DD) { src = W1; dst = g_W1h; off = j - LL * DD * HD; }
        else                                      { src = W2; dst = g_W2h; off = j - LL * DD * HD - LL * DD * DD; }
        float2 v = *(const float2*)(src + off);
        *(__half2*)(dst + off) = __floats2half2_rn(v.x, v.y);
    }
    if (i < NV) g_deg[i] = 1;
    if (blockIdx.x == 0) {
        __shared__ unsigned acc;
        if (threadIdx.x == 0) acc = 0u;
        __syncthreads();
        unsigned v = 0;
        for (int k = threadIdx.x; k < 2048; k += 256) v |= ei_w[2 * k + 1];
        if (v) atomicOr(&acc, 1u);
        __syncthreads();
        if (threadIdx.x == 0) g_is64 = (acc == 0u) ? 1 : 0;
    }
}

// ---------------- CSR build ----------------
__global__ void k_count(const void* ei) {
    int e = (blockIdx.x * 256 + threadIdx.x) * 2;
    if (e < EE) {
        int d0, d1;
        if (g_is64) {
            longlong2 v = ((const longlong2*)ei)[(EE + e) >> 1];
            d0 = (int)v.x; d1 = (int)v.y;
        } else {
            int2 v = ((const int2*)ei)[(EE + e) >> 1];
            d0 = v.x; d1 = v.y;
        }
        atomicAdd(&g_deg[d0], 1);
        atomicAdd(&g_deg[d1], 1);
    }
}

__global__ __launch_bounds__(1024) void k_scan() {
    const int PER = 20;
    __shared__ int wsum[32];
    int t = threadIdx.x, lane = t & 31, w = t >> 5;
    int v[PER];
    int base = t * PER;
    int run = 0;
    if (base < NV) {
        const int4* p = (const int4*)(g_deg + base);
#pragma unroll
        for (int q = 0; q < 5; q++) {
            int4 d = p[q];
            run += d.x; v[q * 4 + 0] = run;
            run += d.y; v[q * 4 + 1] = run;
            run += d.z; v[q * 4 + 2] = run;
            run += d.w; v[q * 4 + 3] = run;
        }
    } else {
#pragma unroll
        for (int q = 0; q < PER; q++) v[q] = 0;
    }
    int tot = run, sc = tot;
#pragma unroll
    for (int o = 1; o < 32; o <<= 1) {
        int u = __shfl_up_sync(0xffffffffu, sc, o);
        if (lane >= o) sc += u;
    }
    if (lane == 31) wsum[w] = sc;
    __syncthreads();
    if (w == 0) {
        int s = wsum[lane];
#pragma unroll
        for (int o = 1; o < 32; o <<= 1) {
            int u = __shfl_up_sync(0xffffffffu, s, o);
            if (lane >= o) s += u;
        }
        wsum[lane] = s;
    }
    __syncthreads();
    int throff = ((w > 0) ? wsum[w - 1] : 0) + sc - tot;
    if (t == 0) g_rowptr[0] = 0;
    if (base < NV) {
#pragma unroll
        for (int q = 0; q < PER; q++) {
            int idx = base + q;
            int startq = throff + (q > 0 ? v[q - 1] : 0);
            g_rowptr[idx + 1] = throff + v[q];
            g_col[startq] = idx;        // self loop at slot 0
            g_cursor[idx] = startq + 1;
        }
    }
}
__global__ void k_scatter(const void* ei) {
    int e = (blockIdx.x * 256 + threadIdx.x) * 2;
    if (e < EE) {
        int s0, s1, d0, d1;
        if (g_is64) {
            longlong2 sv = ((const longlong2*)ei)[e >> 1];
            longlong2 dv = ((const longlong2*)ei)[(EE + e) >> 1];
            s0 = (int)sv.x; s1 = (int)sv.y; d0 = (int)dv.x; d1 = (int)dv.y;
        } else {
            int2 sv = ((const int2*)ei)[e >> 1];
            int2 dv = ((const int2*)ei)[(EE + e) >> 1];
            s0 = sv.x; s1 = sv.y; d0 = dv.x; d1 = dv.y;
        }
        g_col[atomicAdd(&g_cursor[d0], 1)] = s0;
        g_col[atomicAdd(&g_cursor[d1], 1)] = s1;
    }
}

// ---------------- fp16 tensor-core GEMM: block tile 128x64, warp tile 32x32 ----------------
// 8 warps as (wr 0..3) x (wc 0..1); acc[2][2] = 32 regs -> ~79 regs -> 3 CTAs/SM.
// smem: As 128x136 h (34816) + Bs 128x72 h (18432) = 53248; epilogue stage
// per-warp 32x36 f32 (8*4608 = 36864) aliases front.
#define GSMEM 53248

__global__ __launch_bounds__(256, 3) void gemm_h(
    const __half* __restrict__ A, const __half* __restrict__ B,
    __half* __restrict__ Ch, int Ncols)
{
    extern __shared__ char dsm[];
    __half* As = (__half*)dsm;
    __half* Bs = As + 128 * 136;
    float*  stage = (float*)dsm;

    int bm = blockIdx.y * 128, bn = blockIdx.x * 64;
    int t = threadIdx.x, warp = t >> 5, lane = t & 31;
    int wr = warp & 3, wc = warp >> 2;

    wmma::fragment<wmma::accumulator, 16, 16, 16, float> acc[2][2];
#pragma unroll
    for (int fr = 0; fr < 2; fr++)
#pragma unroll
        for (int fc = 0; fc < 2; fc++)
            wmma::fill_fragment(acc[fr][fc], 0.f);

#pragma unroll
    for (int i = 0; i < 8; i++) {                 // A: 128 rows x 16 uint4
        int idx = t + i * 256;
        int r = idx >> 4, c8 = (idx & 15) * 8;
        *(uint4*)(As + r * 136 + c8) = *(const uint4*)(A + (size_t)(bm + r) * 128 + c8);
    }
#pragma unroll
    for (int i = 0; i < 4; i++) {                 // B: 128 rows x 8 uint4
        int idx = t + i * 256;
        int r = idx >> 3, c8 = (idx & 7) * 8;
        *(uint4*)(Bs + r * 72 + c8) = *(const uint4*)(B + (size_t)r * Ncols + bn + c8);
    }
    __syncthreads();

#pragma unroll
    for (int k = 0; k < 8; k++) {
        wmma::fragment<wmma::matrix_a, 16, 16, 16, __half, wmma::row_major> af[2];
        wmma::fragment<wmma::matrix_b, 16, 16, 16, __half, wmma::row_major> bf[2];
#pragma unroll
        for (int fr = 0; fr < 2; fr++)
            wmma::load_matrix_sync(af[fr], &As[(wr * 32 + fr * 16) * 136 + k * 16], 136);
#pragma unroll
        for (int fc = 0; fc < 2; fc++)
            wmma::load_matrix_sync(bf[fc], &Bs[(k * 16) * 72 + wc * 32 + fc * 16], 72);
#pragma unroll
        for (int fr = 0; fr < 2; fr++)
#pragma unroll
            for (int fc = 0; fc < 2; fc++)
                wmma::mma_sync(acc[fr][fc], af[fr], bf[fc], acc[fr][fc]);
    }
    __syncthreads();

    float* ws = stage + warp * 1152;              // 32x36 per warp
#pragma unroll
    for (int fr = 0; fr < 2; fr++)
#pragma unroll
        for (int fc = 0; fc < 2; fc++)
            wmma::store_matrix_sync(&ws[fr * 16 * 36 + fc * 16], acc[fr][fc], 36,
                                    wmma::mem_row_major);
    __syncwarp();
    for (int i = lane; i < 32 * 8; i += 32) {
        int r = i >> 3, c4 = (i & 7) * 4;
        __half2 h0 = __floats2half2_rn(ws[r * 36 + c4], ws[r * 36 + c4 + 1]);
        __half2 h1 = __floats2half2_rn(ws[r * 36 + c4 + 2], ws[r * 36 + c4 + 3]);
        uint2 packed;
        packed.x = *(unsigned*)&h0;
        packed.y = *(unsigned*)&h1;
        *(uint2*)(Ch + (size_t)(bm + wr * 32 + r) * Ncols + bn + wc * 32 + c4) = packed;
    }
}

// ---------------- fused FFN, M-tile = 64 ----------------
#define FM 64
#define FTILES (NV2 / FM)
#define FSMEM 69632

__global__ __launch_bounds__(256) void k_ffn(
    const __half* __restrict__ W1, const __half* __restrict__ W2,
    const float* __restrict__ b1, const float* __restrict__ b2,
    const float* __restrict__ nw, float* __restrict__ outF)
{
    extern __shared__ char dsm[];
    __half* As = (__half*)dsm;                 // 64x136
    __half* Ws = As + FM * 136;                // 128x136
    float*  stage = (float*)dsm;               // 64x132
    __half* Hs = (__half*)(dsm + 52224);       // 64x136
    float*  Brep = (float*)(dsm + 52224);      // 16x136

    int bm = blockIdx.x * FM;
    int t = threadIdx.x, warp = t >> 5, lane = t & 31;
    int wc = warp;

    for (int i = t; i < 16 * 128; i += 256) {
        int r = i >> 7, c = i & 127;
        Brep[r * 136 + c] = b1[c];
    }
#pragma unroll
    for (int i = 0; i < 4; i++) {
        int idx = t + i * 256;
        int r = idx >> 4, c8 = (idx & 15) * 8;
        *(uint4*)(As + r * 136 + c8) = *(const uint4*)(g_xh + (size_t)(bm + r) * 128 + c8);
    }
#pragma unroll
    for (int i = 0; i < 8; i++) {
        int idx = t + i * 256;
        int r = idx >> 4, c8 = (idx & 15) * 8;
        *(uint4*)(Ws + r * 136 + c8) = *(const uint4*)(W1 + (size_t)r * 128 + c8);
    }
    __syncthreads();

    wmma::fragment<wmma::accumulator, 16, 16, 16, float> acc[4];
#pragma unroll
    for (int fr = 0; fr < 4; fr++)
        wmma::load_matrix_sync(acc[fr], &Brep[wc * 16], 136, wmma::mem_row_major);

#pragma unroll
    for (int k = 0; k < 8; k++) {
        wmma::fragment<wmma::matrix_a, 16, 16, 16, __half, wmma::row_major> af[4];
        wmma::fragment<wmma::matrix_b, 16, 16, 16, __half, wmma::row_major> bf;
#pragma unroll
        for (int fr = 0; fr < 4; fr++)
            wmma::load_matrix_sync(af[fr], &As[(fr * 16) * 136 + k * 16], 136);
        wmma::load_matrix_sync(bf, &Ws[(k * 16) * 136 + wc * 16], 136);
#pragma unroll
        for (int fr = 0; fr < 4; fr++)
            wmma::mma_sync(acc[fr], af[fr], bf, acc[fr]);
    }
    __syncthreads();

#pragma unroll
    for (int fr = 0; fr < 4; fr++) {
#pragma unroll
        for (int i = 0; i < acc[fr].num_elements; i++)
            acc[fr].x[i] = fmaxf(acc[fr].x[i], 0.f);
        wmma::store_matrix_sync(&stage[(fr * 16) * 132 + wc * 16], acc[fr], 132,
                                wmma::mem_row_major);
    }
    __syncthreads();

    for (int i = t; i < FM * 32; i += 256) {
        int r = i >> 5, c4 = (i & 31) * 4;
        float4 v = *(const float4*)&stage[r * 132 + c4];
        __half2 h0 = __floats2half2_rn(v.x, v.y);
        __half2 h1 = __floats2half2_rn(v.z, v.w);
        uint2 packed;
        packed.x = *(unsigned*)&h0;
        packed.y = *(unsigned*)&h1;
        *(uint2*)(Hs + r * 136 + c4) = packed;
    }
    __syncthreads();

#pragma unroll
    for (int i = 0; i < 8; i++) {
        int idx = t + i * 256;
        int r = idx >> 4, c8 = (idx & 15) * 8;
        *(uint4*)(Ws + r * 136 + c8) = *(const uint4*)(W2 + (size_t)r * 128 + c8);
    }
    __syncthreads();

#pragma unroll
    for (int fr = 0; fr < 4; fr++)
        wmma::fill_fragment(acc[fr], 0.f);

#pragma unroll
    for (int k = 0; k < 8; k++) {
        wmma::fragment<wmma::matrix_a, 16, 16, 16, __half, wmma::row_major> af[4];
        wmma::fragment<wmma::matrix_b, 16, 16, 16, __half, wmma::row_major> bf;
#pragma unroll
        for (int fr = 0; fr < 4; fr++)
            wmma::load_matrix_sync(af[fr], &Hs[(fr * 16) * 136 + k * 16], 136);
        wmma::load_matrix_sync(bf, &Ws[(k * 16) * 136 + wc * 16], 136);
#pragma unroll
        for (int fr = 0; fr < 4; fr++)
            wmma::mma_sync(acc[fr], af[fr], bf, acc[fr]);
    }
    __syncthreads();

#pragma unroll
    for (int fr = 0; fr < 4; fr++)
        wmma::store_matrix_sync(&stage[(fr * 16) * 132 + wc * 16], acc[fr], 132,
                                wmma::mem_row_major);
    __syncthreads();

    float4 nwv = *(const float4*)&nw[lane * 4];
    float4 b2v = *(const float4*)&b2[lane * 4];
    for (int r = warp; r < FM; r += 8) {
        size_t row = (size_t)(bm + r);
        float4 xr = *(const float4*)&g_x[row * 128 + lane * 4];
        float4 st = *(const float4*)&stage[r * 132 + lane * 4];
        float v0 = xr.x + st.x + b2v.x, v1 = xr.y + st.y + b2v.y;
        float v2 = xr.z + st.z + b2v.z, v3 = xr.w + st.w + b2v.w;
        float ss = v0 * v0 + v1 * v1 + v2 * v2 + v3 * v3;
#pragma unroll
        for (int o = 16; o; o >>= 1) ss += __shfl_xor_sync(0xffffffffu, ss, o);
        float rr = rsqrtf(ss * (1.0f / DD) + EPS_);
        float o0 = v0 * rr * nwv.x, o1 = v1 * rr * nwv.y;
        float o2 = v2 * rr * nwv.z, o3 = v3 * rr * nwv.w;
        if (outF) {
            if (row < NV)
                *(float4*)&outF[row * 128 + lane * 4] = make_float4(o0, o1, o2, o3);
        } else {
            *(float4*)&g_x[row * 128 + lane * 4] = make_float4(o0, o1, o2, o3);
            __half2 h0 = __floats2half2_rn(o0, o1);
            __half2 h1 = __floats2half2_rn(o2, o3);
            uint2 packed;
            packed.x = *(unsigned*)&h0;
            packed.y = *(unsigned*)&h1;
            *(uint2*)&g_xh[row * 128 + lane * 4] = packed;
        }
    }
}

// ---------------- attention dots ----------------
__global__ __launch_bounds__(128) void k_dots(const float* __restrict__ att_s,
                                              const float* __restrict__ att_d) {
    int warp = threadIdx.x >> 5, lane = threadIdx.x & 31;
    int n = blockIdx.x * 4 + warp;
    if (n >= NV) return;
    const __half* xpr = g_xph + (size_t)n * HD;
#pragma unroll
    for (int h = 0; h < 4; h++) {
        uint2 raw = *(const uint2*)(xpr + h * 128 + lane * 4);
        float2 f0 = __half22float2(*(__half2*)&raw.x);
        float2 f1 = __half22float2(*(__half2*)&raw.y);
        float4 as = *(const float4*)&att_s[h * 128 + lane * 4];
        float4 ad = *(const float4*)&att_d[h * 128 + lane * 4];
        float ps = f0.x * as.x + f0.y * as.y + f1.x * as.z + f1.y * as.w;
        float pd = f0.x * ad.x + f0.y * ad.y + f1.x * ad.z + f1.y * ad.w;
#pragma unroll
        for (int o = 16; o; o >>= 1) {
            ps += __shfl_xor_sync(0xffffffffu, ps, o);
            pd += __shfl_xor_sync(0xffffffffu, pd, o);
        }
        if (lane == 0) {
            g_as[n * 4 + h] = ps;
            g_ad[n * 4 + h] = pd;
        }
    }
}

__device__ __forceinline__ float lrelu(float x) { return x > 0.f ? x : 0.2f * x; }

__device__ __forceinline__ void comb(float& m, float& s, float m2, float s2) {
    float M = fmaxf(m, m2);
    s = s * __expf(m - M) + s2 * __expf(m2 - M);
    m = M;
}

// ---------------- fused GAT aggregation: warp-per-head ----------------
__global__ __launch_bounds__(128) void k_agg(const float* __restrict__ bias,
                                             const float* __restrict__ nw) {
    int n = blockIdx.x, t = threadIdx.x;
    int w = t >> 5, lane = t & 31;
    int start = g_rowptr[n];
    int deg = g_rowptr[n + 1] - start;

    __shared__ float xatt[4][128];
    __shared__ float sred[4];

    float adv = g_ad[n * 4 + w];

    float m = -1e30f, s = 0.f;
    int src0 = 0; float e0 = -1e30f;
    for (int j = lane; j < deg; j += 32) {
        int src = g_col[start + j];
        float e = lrelu(g_as[src * 4 + w] + adv);
        if (j < 32) { src0 = src; e0 = e; }
        comb(m, s, e, 1.f);
    }
#pragma unroll
    for (int o = 16; o; o >>= 1) {
        float m2 = __shfl_xor_sync(0xffffffffu, m, o);
        float s2 = __shfl_xor_sync(0xffffffffu, s, o);
        comb(m, s, m2, s2);
    }
    float M = m;
    float inv = 1.f / s;

    float4 acc = make_float4(0.f, 0.f, 0.f, 0.f);
    for (int c0 = 0; c0 < deg; c0 += 32) {
        int j = c0 + lane;
        int src; float al;
        if (c0 == 0) {
            src = src0;
            al = (lane < deg) ? __expf(e0 - M) * inv : 0.f;
        } else {
            src = 0; al = 0.f;
            if (j < deg) {
                src = g_col[start + j];
                al = __expf(lrelu(g_as[src * 4 + w] + adv) - M) * inv;
            }
        }
        int cnt = min(32, deg - c0);
        for (int jj = 0; jj < cnt; jj++) {
            float a = __shfl_sync(0xffffffffu, al, jj);
            int sj = __shfl_sync(0xffffffffu, src, jj);
            uint2 raw = *(const uint2*)(g_xph + (size_t)sj * HD + w * 128 + lane * 4);
            float2 f0 = __half22float2(*(__half2*)&raw.x);
            float2 f1 = __half22float2(*(__half2*)&raw.y);
            acc.x += a * f0.x;
            acc.y += a * f0.y;
            acc.z += a * f1.x;
            acc.w += a * f1.y;
        }
    }
    *(float4*)&xatt[w][lane * 4] = acc;
    __syncthreads();

    float a = 0.25f * (xatt[0][t] + xatt[1][t] + xatt[2][t] + xatt[3][t]);
    float v = g_x[n * DD + t] + a + bias[t];
    float ss = v * v;
#pragma unroll
    for (int o = 16; o; o >>= 1) ss += __shfl_xor_sync(0xffffffffu, ss, o);
    if (lane == 0) sred[w] = ss;
    __syncthreads();
    float tot = sred[0] + sred[1] + sred[2] + sred[3];
    float r = rsqrtf(tot * (1.0f / DD) + EPS_);
    float o = v * r * nw[t];
    g_x[n * DD + t] = o;
    g_xh[n * DD + t] = __float2half(o);
}

// ---------------- host ----------------
extern "C" void kernel_launch(void* const* d_in, const int* in_sizes, int n_in,
                              void* d_out, int out_size) {
    const float* x        = (const float*)d_in[0];
    const float* W_gat    = (const float*)d_in[1];
    const float* att_src  = (const float*)d_in[2];
    const float* att_dst  = (const float*)d_in[3];
    const float* bias_gat = (const float*)d_in[4];
    const float* W1       = (const float*)d_in[5];
    const float* b1       = (const float*)d_in[6];
    const float* W2       = (const float*)d_in[7];
    const float* b2       = (const float*)d_in[8];
    const float* n1w      = (const float*)d_in[9];
    const float* n2w      = (const float*)d_in[10];
    const void*  ei       = d_in[11];

    static cudaStream_t s2 = nullptr;
    static cudaEvent_t evA = nullptr, evB = nullptr;
    if (!s2) {
        cudaFuncSetAttribute(gemm_h, cudaFuncAttributeMaxDynamicSharedMemorySize, GSMEM);
        cudaFuncSetAttribute(k_ffn, cudaFuncAttributeMaxDynamicSharedMemorySize, FSMEM);
        cudaStreamCreate(&s2);
        cudaEventCreateWithFlags(&evA, cudaEventDisableTiming);
        cudaEventCreateWithFlags(&evB, cudaEventDisableTiming);
    }

    __half *xh, *xph, *Wg, *W1h, *W2h;
    cudaGetSymbolAddress((void**)&xh,  g_xh);
    cudaGetSymbolAddress((void**)&xph, g_xph);
    cudaGetSymbolAddress((void**)&Wg,  g_Wg);
    cudaGetSymbolAddress((void**)&W1h, g_W1h);
    cudaGetSymbolAddress((void**)&W2h, g_W2h);

    // main stream: setup -> gemm0 -> dots0 -> (join) agg0 -> ffn0 -> ...
    // side stream s2: CSR build (count -> scan -> scatter), forked after setup.
    k_setup<<<2500, 256>>>((const float4*)x, W_gat, W1, W2, (const unsigned*)ei);
    cudaEventRecord(evA);
    cudaStreamWaitEvent(s2, evA, 0);
    k_count<<<(EE / 2 + 255) / 256, 256, 0, s2>>>(ei);
    k_scan<<<1, 1024, 0, s2>>>();
    gemm_h<<<dim3(HD / 64, MTILES), 256, GSMEM>>>(xh, Wg, xph, HD);   // 4th launch
    k_scatter<<<(EE / 2 + 255) / 256, 256, 0, s2>>>(ei);
    cudaEventRecord(evB, s2);
    k_dots<<<(NV + 3) / 4, 128>>>(att_src, att_dst);
    cudaStreamWaitEvent(0, evB, 0);

    for (int i = 0; i < LL; i++) {
        if (i > 0) {
            gemm_h<<<dim3(HD / 64, MTILES), 256, GSMEM>>>(
                xh, Wg + (size_t)i * DD * HD, xph, HD);
            k_dots<<<(NV + 3) / 4, 128>>>(att_src + i * HD, att_dst + i * HD);
        }
        k_agg<<<NV, 128>>>(bias_gat + i * DD, n1w + i * DD);
        k_ffn<<<FTILES, 256, FSMEM>>>(
            W1h + (size_t)i * DD * DD, W2h + (size_t)i * DD * DD,
            b1 + i * DD, b2 + i * DD, n2w + i * DD,
            (i == LL - 1) ? (float*)d_out : nullptr);
    }
}